// round 1
// baseline (speedup 1.0000x reference)
#include <cuda_runtime.h>
#include <math.h>

#define BB   2
#define SS   4096
#define DD   512
#define HH   8
#define HDD  64
#define LAT  64

// ---------------- scratch (static device globals; no allocs) ----------------
__device__ float g_part[BB * 32 * DD];          // mean partial sums
__device__ float g_lat [BB * DD];               // latent projection (b, 512)
__device__ float g_q   [BB * HH * SS * HDD];    // (b,h,s,hd)
__device__ float g_k   [BB * HH * SS * HDD];
__device__ float g_v   [BB * HH * SS * HDD];
__device__ float g_ctx [BB * SS * DD];          // (b,s,d)

// ---------------- 1) mean over sequence: partial sums ----------------
__global__ void mean_partial(const float* __restrict__ x) {
    int bx = blockIdx.x;            // b*32 + split
    int b  = bx >> 5;
    int sp = bx & 31;
    int t  = threadIdx.x;           // 512 threads, one per d
    const int chunk = SS / 32;      // 128
    const float* p = x + ((long)b * SS + (long)sp * chunk) * DD + t;
    float s = 0.f;
#pragma unroll 4
    for (int i = 0; i < chunk; i++) s += p[(long)i * DD];
    g_part[(long)bx * DD + t] = s;
}

// ---------------- 2) VAE MLP: xm -> h1 -> h2 -> mu/logvar -> z -> latent ----
__global__ void vae_kernel(const float* __restrict__ eps,
                           const float* __restrict__ we1, const float* __restrict__ be1,
                           const float* __restrict__ we2, const float* __restrict__ be2,
                           const float* __restrict__ wmu, const float* __restrict__ bmu,
                           const float* __restrict__ wlv, const float* __restrict__ blv,
                           const float* __restrict__ wf,  const float* __restrict__ bf,
                           float* __restrict__ out) {
    int b = blockIdx.x;
    int t = threadIdx.x;            // 512
    __shared__ float xm[DD];
    __shared__ float h1[256];
    __shared__ float h2[128];
    __shared__ float z [LAT];

    float s = 0.f;
#pragma unroll
    for (int i = 0; i < 32; i++) s += g_part[((long)b * 32 + i) * DD + t];
    xm[t] = s * (1.0f / (float)SS);
    __syncthreads();

    if (t < 256) {
        float a = be1[t];
        const float* w = we1 + (long)t * DD;
#pragma unroll 8
        for (int k = 0; k < DD; k++) a += xm[k] * w[k];
        h1[t] = fmaxf(a, 0.f);
    }
    __syncthreads();

    if (t < 128) {
        float a = be2[t];
        const float* w = we2 + (long)t * 256;
#pragma unroll 8
        for (int k = 0; k < 256; k++) a += h1[k] * w[k];
        h2[t] = fmaxf(a, 0.f);
    }
    __syncthreads();

    if (t < LAT) {
        float mu = bmu[t], lv = blv[t];
        const float* w1 = wmu + (long)t * 128;
        const float* w2 = wlv + (long)t * 128;
#pragma unroll 8
        for (int k = 0; k < 128; k++) { mu += h2[k] * w1[k]; lv += h2[k] * w2[k]; }
        out[(long)BB * SS * DD + b * LAT + t]            = mu;
        out[(long)BB * SS * DD + BB * LAT + b * LAT + t] = lv;
        z[t] = mu + eps[b * LAT + t] * expf(0.5f * lv);
    }
    __syncthreads();

    {   // latent projection: (512,64) @ z + bf
        float a = bf[t];
        const float* w = wf + (long)t * LAT;
#pragma unroll
        for (int k = 0; k < LAT; k++) a += z[k] * w[k];
        g_lat[b * DD + t] = a;
    }
}

// ---------------- 3) GEMM: C = A @ W^T + bias (+latent), optional (b,h,s,hd) out
// A: (8192, 512) row-major, W: (512, 512) row-major. 64x64 block, 4x4 per thread.
template <bool ADD_LAT, bool BHSD>
__global__ __launch_bounds__(256) void gemm_proj(const float* __restrict__ A,
                                                 const float* __restrict__ W,
                                                 const float* __restrict__ bias,
                                                 float* __restrict__ out) {
    __shared__ float As[16][68];
    __shared__ float Bs[16][68];
    int tid = threadIdx.x;
    int tx = tid & 15, ty = tid >> 4;
    int m0 = blockIdx.x * 64, n0 = blockIdx.y * 64;
    int lr = tid >> 2;             // 0..63
    int lc = (tid & 3) * 4;        // 0,4,8,12

    float acc[4][4] = {};
    const float* Ap = A + (long)(m0 + lr) * DD + lc;
    const float* Wp = W + (long)(n0 + lr) * DD + lc;

    for (int k0 = 0; k0 < DD; k0 += 16) {
        float4 a4 = *(const float4*)(Ap + k0);
        float4 b4 = *(const float4*)(Wp + k0);
        As[lc + 0][lr] = a4.x; As[lc + 1][lr] = a4.y; As[lc + 2][lr] = a4.z; As[lc + 3][lr] = a4.w;
        Bs[lc + 0][lr] = b4.x; Bs[lc + 1][lr] = b4.y; Bs[lc + 2][lr] = b4.z; Bs[lc + 3][lr] = b4.w;
        __syncthreads();
#pragma unroll
        for (int kk = 0; kk < 16; kk++) {
            float4 ra = *(const float4*)&As[kk][4 * ty];
            float4 rb = *(const float4*)&Bs[kk][4 * tx];
            float a_[4] = {ra.x, ra.y, ra.z, ra.w};
            float b_[4] = {rb.x, rb.y, rb.z, rb.w};
#pragma unroll
            for (int i = 0; i < 4; i++)
#pragma unroll
                for (int j = 0; j < 4; j++) acc[i][j] += a_[i] * b_[j];
        }
        __syncthreads();
    }

    int c0 = n0 + 4 * tx;
    float bz0 = bias[c0], bz1 = bias[c0 + 1], bz2 = bias[c0 + 2], bz3 = bias[c0 + 3];
#pragma unroll
    for (int i = 0; i < 4; i++) {
        int row = m0 + 4 * ty + i;
        int b = row >> 12;          // row / 4096
        int sidx = row & 4095;
        float v0 = acc[i][0] + bz0;
        float v1 = acc[i][1] + bz1;
        float v2 = acc[i][2] + bz2;
        float v3 = acc[i][3] + bz3;
        if (ADD_LAT) {
            v0 += g_lat[b * DD + c0];
            v1 += g_lat[b * DD + c0 + 1];
            v2 += g_lat[b * DD + c0 + 2];
            v3 += g_lat[b * DD + c0 + 3];
        }
        float4 o = make_float4(v0, v1, v2, v3);
        if (BHSD) {
            int h  = n0 >> 6;
            int hd = c0 & 63;
            *(float4*)&out[(((long)(b * HH + h) * SS + sidx) * HDD) + hd] = o;
        } else {
            *(float4*)&out[(long)row * DD + c0] = o;
        }
    }
}

// ---------------- 4) flash attention: 64 queries x 64 keys tiles, fp32 -------
__global__ __launch_bounds__(256) void flash_attn() {
    extern __shared__ float sm[];
    float* Qs = sm;                  // [d][m], stride 68
    float* Ks = sm + 64 * 68;        // [d][n], stride 68 (aliased as Ps[n][m])
    float* Vs = sm + 2 * 64 * 68;    // [j][dv], stride 68

    int tid = threadIdx.x;
    int tx = tid & 15, ty = tid >> 4;
    int bh = blockIdx.y;             // b*8 + h
    int m0 = blockIdx.x * 64;
    int lr = tid >> 2;               // 0..63
    int lc = (tid & 3) * 4;          // 0,4,8,12

    const float* Qg = g_q + ((long)bh * SS + m0) * HDD;
    const float* Kg = g_k + (long)bh * SS * HDD;
    const float* Vg = g_v + (long)bh * SS * HDD;

    // load Q tile transposed: Qs[d][m]
#pragma unroll
    for (int cc = 0; cc < 64; cc += 16) {
        float4 q4 = *(const float4*)&Qg[(long)lr * HDD + lc + cc];
        Qs[(lc + cc + 0) * 68 + lr] = q4.x;
        Qs[(lc + cc + 1) * 68 + lr] = q4.y;
        Qs[(lc + cc + 2) * 68 + lr] = q4.z;
        Qs[(lc + cc + 3) * 68 + lr] = q4.w;
    }

    float oacc[4][4] = {};
    float mrow[4] = {-1e30f, -1e30f, -1e30f, -1e30f};
    float lrow[4] = {};

    for (int n0 = 0; n0 < SS; n0 += 64) {
        // load K (transposed) and V
#pragma unroll
        for (int cc = 0; cc < 64; cc += 16) {
            float4 k4 = *(const float4*)&Kg[(long)(n0 + lr) * HDD + lc + cc];
            Ks[(lc + cc + 0) * 68 + lr] = k4.x;
            Ks[(lc + cc + 1) * 68 + lr] = k4.y;
            Ks[(lc + cc + 2) * 68 + lr] = k4.z;
            Ks[(lc + cc + 3) * 68 + lr] = k4.w;
            float4 v4 = *(const float4*)&Vg[(long)(n0 + lr) * HDD + lc + cc];
            *(float4*)&Vs[lr * 68 + lc + cc] = v4;
        }
        __syncthreads();

        // S = Q @ K^T
        float acc[4][4] = {};
#pragma unroll 8
        for (int d = 0; d < 64; d++) {
            float4 ra = *(const float4*)&Qs[d * 68 + 4 * ty];
            float4 rb = *(const float4*)&Ks[d * 68 + 4 * tx];
            float a_[4] = {ra.x, ra.y, ra.z, ra.w};
            float b_[4] = {rb.x, rb.y, rb.z, rb.w};
#pragma unroll
            for (int i = 0; i < 4; i++)
#pragma unroll
                for (int j = 0; j < 4; j++) acc[i][j] += a_[i] * b_[j];
        }
        __syncthreads();   // done reading Ks before it becomes Ps

        // online softmax (rows 4ty..4ty+3, stats reduced across 16-lane tx group)
        float p[4][4];
#pragma unroll
        for (int i = 0; i < 4; i++) {
#pragma unroll
            for (int j = 0; j < 4; j++) acc[i][j] *= 0.125f;   // 1/sqrt(64)
            float tm = fmaxf(fmaxf(acc[i][0], acc[i][1]), fmaxf(acc[i][2], acc[i][3]));
            tm = fmaxf(tm, __shfl_xor_sync(0xffffffffu, tm, 1));
            tm = fmaxf(tm, __shfl_xor_sync(0xffffffffu, tm, 2));
            tm = fmaxf(tm, __shfl_xor_sync(0xffffffffu, tm, 4));
            tm = fmaxf(tm, __shfl_xor_sync(0xffffffffu, tm, 8));
            float mn   = fmaxf(mrow[i], tm);
            float corr = __expf(mrow[i] - mn);
            mrow[i] = mn;
            float ts = 0.f;
#pragma unroll
            for (int j = 0; j < 4; j++) { p[i][j] = __expf(acc[i][j] - mn); ts += p[i][j]; }
            ts += __shfl_xor_sync(0xffffffffu, ts, 1);
            ts += __shfl_xor_sync(0xffffffffu, ts, 2);
            ts += __shfl_xor_sync(0xffffffffu, ts, 4);
            ts += __shfl_xor_sync(0xffffffffu, ts, 8);
            lrow[i] = lrow[i] * corr + ts;
#pragma unroll
            for (int j = 0; j < 4; j++) oacc[i][j] *= corr;
        }

        // store P transposed into Ks buffer: Ps[n][m]
#pragma unroll
        for (int j = 0; j < 4; j++) {
            float4 pv = make_float4(p[0][j], p[1][j], p[2][j], p[3][j]);
            *(float4*)&Ks[(4 * tx + j) * 68 + 4 * ty] = pv;
        }
        __syncthreads();

        // O += P @ V
#pragma unroll 8
        for (int jj = 0; jj < 64; jj++) {
            float4 ra = *(const float4*)&Ks[jj * 68 + 4 * ty];   // P rows
            float4 rb = *(const float4*)&Vs[jj * 68 + 4 * tx];   // V cols
            float a_[4] = {ra.x, ra.y, ra.z, ra.w};
            float b_[4] = {rb.x, rb.y, rb.z, rb.w};
#pragma unroll
            for (int i = 0; i < 4; i++)
#pragma unroll
                for (int j = 0; j < 4; j++) oacc[i][j] += a_[i] * b_[j];
        }
        __syncthreads();   // before next tile overwrites Ks/Vs
    }

    // normalize + write ctx in (b,s,d) layout
    int b = bh >> 3, h = bh & 7;
#pragma unroll
    for (int i = 0; i < 4; i++) {
        float inv = 1.0f / lrow[i];
        float4 o = make_float4(oacc[i][0] * inv, oacc[i][1] * inv,
                               oacc[i][2] * inv, oacc[i][3] * inv);
        long row = (long)b * SS + m0 + 4 * ty + i;
        *(float4*)&g_ctx[row * DD + h * HDD + 4 * tx] = o;
    }
}

// ---------------- launch ----------------
extern "C" void kernel_launch(void* const* d_in, const int* in_sizes, int n_in,
                              void* d_out, int out_size) {
    const float* x   = (const float*)d_in[0];
    const float* eps = (const float*)d_in[1];
    const float* wq  = (const float*)d_in[2];  const float* bq  = (const float*)d_in[3];
    const float* wk  = (const float*)d_in[4];  const float* bk  = (const float*)d_in[5];
    const float* wv  = (const float*)d_in[6];  const float* bv  = (const float*)d_in[7];
    const float* wo  = (const float*)d_in[8];  const float* bo  = (const float*)d_in[9];
    const float* we1 = (const float*)d_in[10]; const float* be1 = (const float*)d_in[11];
    const float* we2 = (const float*)d_in[12]; const float* be2 = (const float*)d_in[13];
    const float* wmu = (const float*)d_in[14]; const float* bmu = (const float*)d_in[15];
    const float* wlv = (const float*)d_in[16]; const float* blv = (const float*)d_in[17];
    const float* wf  = (const float*)d_in[18]; const float* bf  = (const float*)d_in[19];
    float* out = (float*)d_out;

    void *pq, *pk, *pv, *pctx;
    cudaGetSymbolAddress(&pq,  g_q);
    cudaGetSymbolAddress(&pk,  g_k);
    cudaGetSymbolAddress(&pv,  g_v);
    cudaGetSymbolAddress(&pctx, g_ctx);

    const int FLASH_SMEM = 3 * 64 * 68 * 4;   // 52224 bytes
    cudaFuncSetAttribute(flash_attn, cudaFuncAttributeMaxDynamicSharedMemorySize, FLASH_SMEM);

    // 1) mean partials + 2) VAE MLP (writes mu/logvar tail + g_lat)
    mean_partial<<<BB * 32, DD>>>(x);
    vae_kernel<<<BB, DD>>>(eps, we1, be1, we2, be2, wmu, bmu, wlv, blv, wf, bf, out);

    // 3) projections
    dim3 gg((BB * SS) / 64, DD / 64);
    gemm_proj<true,  true ><<<gg, 256>>>(x, wq, bq, (float*)pq);
    gemm_proj<true,  true ><<<gg, 256>>>(x, wk, bk, (float*)pk);
    gemm_proj<false, true ><<<gg, 256>>>(x, wv, bv, (float*)pv);

    // 4) attention
    flash_attn<<<dim3(SS / 64, BB * HH), 256, FLASH_SMEM>>>();

    // 5) output projection -> d_out[0 .. B*S*D)
    gemm_proj<false, false><<<gg, 256>>>((float*)pctx, wo, bo, out);
}

// round 2
// speedup vs baseline: 1.8727x; 1.8727x over previous
#include <cuda_runtime.h>
#include <math.h>
#include <stdint.h>

#define BB   2
#define SS   4096
#define DD   512
#define HH   8
#define HDD  64
#define LAT  64

// ---------------- scratch (static device globals; no allocs) ----------------
__device__ float g_part[BB * 32 * DD];          // mean partial sums
__device__ float g_lat [BB * DD];               // latent projection (b, 512)
__device__ float g_q   [BB * HH * SS * HDD];    // (b,h,s,hd)
__device__ float g_k   [BB * HH * SS * HDD];
__device__ float g_v   [BB * HH * SS * HDD];
__device__ float g_ctx [BB * SS * DD];          // (b,s,d)

// ---------------- helpers ----------------
__device__ __forceinline__ uint32_t f2tf(float f) {
    uint32_t r;
    asm("cvt.rna.tf32.f32 %0, %1;" : "=r"(r) : "f"(f));
    return r;
}

__device__ __forceinline__ void mma_tf32(float* c, uint32_t a0, uint32_t a1,
                                         uint32_t a2, uint32_t a3,
                                         uint32_t b0, uint32_t b1) {
    asm volatile(
        "mma.sync.aligned.m16n8k8.row.col.f32.tf32.tf32.f32 "
        "{%0,%1,%2,%3}, {%4,%5,%6,%7}, {%8,%9}, {%0,%1,%2,%3};\n"
        : "+f"(c[0]), "+f"(c[1]), "+f"(c[2]), "+f"(c[3])
        : "r"(a0), "r"(a1), "r"(a2), "r"(a3), "r"(b0), "r"(b1));
}

// ---------------- 1) mean over sequence: partial sums ----------------
__global__ void mean_partial(const float* __restrict__ x) {
    int bx = blockIdx.x;            // b*32 + split
    int b  = bx >> 5;
    int sp = bx & 31;
    int t  = threadIdx.x;           // 512 threads, one per d
    const int chunk = SS / 32;      // 128
    const float* p = x + ((long)b * SS + (long)sp * chunk) * DD + t;
    float s = 0.f;
#pragma unroll 4
    for (int i = 0; i < chunk; i++) s += p[(long)i * DD];
    g_part[(long)bx * DD + t] = s;
}

// ---------------- 2) VAE MLP ----------------
__global__ void vae_kernel(const float* __restrict__ eps,
                           const float* __restrict__ we1, const float* __restrict__ be1,
                           const float* __restrict__ we2, const float* __restrict__ be2,
                           const float* __restrict__ wmu, const float* __restrict__ bmu,
                           const float* __restrict__ wlv, const float* __restrict__ blv,
                           const float* __restrict__ wf,  const float* __restrict__ bf,
                           float* __restrict__ out) {
    int b = blockIdx.x;
    int t = threadIdx.x;            // 512
    __shared__ float xm[DD];
    __shared__ float h1[256];
    __shared__ float h2[128];
    __shared__ float z [LAT];

    float s = 0.f;
#pragma unroll
    for (int i = 0; i < 32; i++) s += g_part[((long)b * 32 + i) * DD + t];
    xm[t] = s * (1.0f / (float)SS);
    __syncthreads();

    if (t < 256) {
        float a = be1[t];
        const float* w = we1 + (long)t * DD;
#pragma unroll 8
        for (int k = 0; k < DD; k++) a += xm[k] * w[k];
        h1[t] = fmaxf(a, 0.f);
    }
    __syncthreads();

    if (t < 128) {
        float a = be2[t];
        const float* w = we2 + (long)t * 256;
#pragma unroll 8
        for (int k = 0; k < 256; k++) a += h1[k] * w[k];
        h2[t] = fmaxf(a, 0.f);
    }
    __syncthreads();

    if (t < LAT) {
        float mu = bmu[t], lv = blv[t];
        const float* w1 = wmu + (long)t * 128;
        const float* w2 = wlv + (long)t * 128;
#pragma unroll 8
        for (int k = 0; k < 128; k++) { mu += h2[k] * w1[k]; lv += h2[k] * w2[k]; }
        out[(long)BB * SS * DD + b * LAT + t]            = mu;
        out[(long)BB * SS * DD + BB * LAT + b * LAT + t] = lv;
        z[t] = mu + eps[b * LAT + t] * expf(0.5f * lv);
    }
    __syncthreads();

    {
        float a = bf[t];
        const float* w = wf + (long)t * LAT;
#pragma unroll
        for (int k = 0; k < LAT; k++) a += z[k] * w[k];
        g_lat[b * DD + t] = a;
    }
}

// ---------------- 3) tf32 tensor-core GEMM: C = A @ W^T + bias (+latent) ----
// A: (8192, 512), W: (512, 512). Block tile 128x64. 8 warps, warp = 16 rows x 64 cols.
template <bool ADD_LAT, bool BHSD>
__global__ __launch_bounds__(256) void gemm_tc(const float* __restrict__ A,
                                               const float* __restrict__ W,
                                               const float* __restrict__ bias,
                                               float* __restrict__ out) {
    extern __shared__ float sm[];
    float* As = sm;                 // [128][68]
    float* Ws = sm + 128 * 68;      // [64][68]

    int tid  = threadIdx.x;
    int lane = tid & 31;
    int wid  = tid >> 5;
    int gID  = lane >> 2;
    int tig  = lane & 3;
    int m0   = blockIdx.x * 128;
    int n0   = blockIdx.y * 64;
    int m0w  = wid * 16;

    float acc[8][4] = {};

    for (int kc = 0; kc < DD; kc += 64) {
        __syncthreads();
        // load A chunk: row = tid>>1 (0..127), cols (tid&1)*32 .. +31
        {
            int r = tid >> 1, c = (tid & 1) * 32;
            const float* Ap = A + (long)(m0 + r) * DD + kc + c;
            float* Ad = As + r * 68 + c;
#pragma unroll
            for (int i = 0; i < 8; i++) {
                float4 v = *(const float4*)(Ap + i * 4);
                Ad[i * 4 + 0] = __uint_as_float(f2tf(v.x));
                Ad[i * 4 + 1] = __uint_as_float(f2tf(v.y));
                Ad[i * 4 + 2] = __uint_as_float(f2tf(v.z));
                Ad[i * 4 + 3] = __uint_as_float(f2tf(v.w));
            }
        }
        // load W chunk: row = tid>>2 (0..63), cols (tid&3)*16 .. +15
        {
            int r = tid >> 2, c = (tid & 3) * 16;
            const float* Wp = W + (long)(n0 + r) * DD + kc + c;
            float* Wd = Ws + r * 68 + c;
#pragma unroll
            for (int i = 0; i < 4; i++) {
                float4 v = *(const float4*)(Wp + i * 4);
                Wd[i * 4 + 0] = __uint_as_float(f2tf(v.x));
                Wd[i * 4 + 1] = __uint_as_float(f2tf(v.y));
                Wd[i * 4 + 2] = __uint_as_float(f2tf(v.z));
                Wd[i * 4 + 3] = __uint_as_float(f2tf(v.w));
            }
        }
        __syncthreads();

#pragma unroll
        for (int ks = 0; ks < 8; ks++) {
            uint32_t a0 = __float_as_uint(As[(m0w + gID)     * 68 + 8 * ks + tig]);
            uint32_t a1 = __float_as_uint(As[(m0w + gID + 8) * 68 + 8 * ks + tig]);
            uint32_t a2 = __float_as_uint(As[(m0w + gID)     * 68 + 8 * ks + tig + 4]);
            uint32_t a3 = __float_as_uint(As[(m0w + gID + 8) * 68 + 8 * ks + tig + 4]);
#pragma unroll
            for (int nb = 0; nb < 8; nb++) {
                uint32_t b0 = __float_as_uint(Ws[(8 * nb + gID) * 68 + 8 * ks + tig]);
                uint32_t b1 = __float_as_uint(Ws[(8 * nb + gID) * 68 + 8 * ks + tig + 4]);
                mma_tf32(acc[nb], a0, a1, a2, a3, b0, b1);
            }
        }
    }

    // epilogue
#pragma unroll
    for (int nb = 0; nb < 8; nb++) {
        int col = n0 + 8 * nb + 2 * tig;
        float bz0 = bias[col], bz1 = bias[col + 1];
#pragma unroll
        for (int rr = 0; rr < 2; rr++) {
            int row = m0 + m0w + gID + 8 * rr;
            int b = row >> 12;
            int sidx = row & 4095;
            float v0 = acc[nb][2 * rr + 0] + bz0;
            float v1 = acc[nb][2 * rr + 1] + bz1;
            if (ADD_LAT) {
                v0 += g_lat[b * DD + col];
                v1 += g_lat[b * DD + col + 1];
            }
            float2 o = make_float2(v0, v1);
            if (BHSD) {
                int h  = col >> 6;
                int hd = col & 63;
                *(float2*)&out[(((long)(b * HH + h) * SS + sidx) * HDD) + hd] = o;
            } else {
                *(float2*)&out[(long)row * DD + col] = o;
            }
        }
    }
}

// ---------------- 4) tf32 tensor-core flash attention -----------------------
// Tile: 128 queries x 64 keys, HD=64. 8 warps, warp = 16-row strip x full 64 cols.
__global__ __launch_bounds__(256) void flash_tc() {
    extern __shared__ float sm[];
    float* Qs = sm;                      // [128][68]  (tf32 bits, pre-scaled 1/8)
    float* Ks = sm + 128 * 68;           // [64][68]
    float* Vs = sm + 128 * 68 + 64 * 68; // [64][72]

    int tid  = threadIdx.x;
    int lane = tid & 31;
    int wid  = tid >> 5;
    int gID  = lane >> 2;
    int tig  = lane & 3;
    int bh   = blockIdx.y;               // b*8 + h
    int m0   = blockIdx.x * 128;
    int m0w  = wid * 16;

    const float* Qg = g_q + ((long)bh * SS + m0) * HDD;
    const float* Kg = g_k + (long)bh * SS * HDD;
    const float* Vg = g_v + (long)bh * SS * HDD;

    // load Q tile -> smem (tf32, * 1/8)
    {
        int r = tid >> 1, c = (tid & 1) * 32;
        const float* Qp = Qg + (long)r * HDD + c;
        float* Qd = Qs + r * 68 + c;
#pragma unroll
        for (int i = 0; i < 8; i++) {
            float4 v = *(const float4*)(Qp + i * 4);
            Qd[i * 4 + 0] = __uint_as_float(f2tf(v.x * 0.125f));
            Qd[i * 4 + 1] = __uint_as_float(f2tf(v.y * 0.125f));
            Qd[i * 4 + 2] = __uint_as_float(f2tf(v.z * 0.125f));
            Qd[i * 4 + 3] = __uint_as_float(f2tf(v.w * 0.125f));
        }
    }
    __syncthreads();

    // preload Q fragments (reused for all key tiles)
    uint32_t qa[8][4];
#pragma unroll
    for (int ks = 0; ks < 8; ks++) {
        qa[ks][0] = __float_as_uint(Qs[(m0w + gID)     * 68 + 8 * ks + tig]);
        qa[ks][1] = __float_as_uint(Qs[(m0w + gID + 8) * 68 + 8 * ks + tig]);
        qa[ks][2] = __float_as_uint(Qs[(m0w + gID)     * 68 + 8 * ks + tig + 4]);
        qa[ks][3] = __float_as_uint(Qs[(m0w + gID + 8) * 68 + 8 * ks + tig + 4]);
    }

    float oacc[8][4] = {};
    float m0r = -1e30f, m1r = -1e30f;
    float l0 = 0.f, l1 = 0.f;

    for (int n0 = 0; n0 < SS; n0 += 64) {
        __syncthreads();   // previous tile's reads of Ks/Vs done
        // load K, V tiles (tf32)
        {
            int r = tid >> 2, c = (tid & 3) * 16;
            const float* Kp = Kg + (long)(n0 + r) * HDD + c;
            const float* Vp = Vg + (long)(n0 + r) * HDD + c;
            float* Kd = Ks + r * 68 + c;
            float* Vd = Vs + r * 72 + c;
#pragma unroll
            for (int i = 0; i < 4; i++) {
                float4 kv = *(const float4*)(Kp + i * 4);
                Kd[i * 4 + 0] = __uint_as_float(f2tf(kv.x));
                Kd[i * 4 + 1] = __uint_as_float(f2tf(kv.y));
                Kd[i * 4 + 2] = __uint_as_float(f2tf(kv.z));
                Kd[i * 4 + 3] = __uint_as_float(f2tf(kv.w));
                float4 vv = *(const float4*)(Vp + i * 4);
                Vd[i * 4 + 0] = __uint_as_float(f2tf(vv.x));
                Vd[i * 4 + 1] = __uint_as_float(f2tf(vv.y));
                Vd[i * 4 + 2] = __uint_as_float(f2tf(vv.z));
                Vd[i * 4 + 3] = __uint_as_float(f2tf(vv.w));
            }
        }
        __syncthreads();

        // ---- S = Q @ K^T  (warp strip: 16 x 64) ----
        float sacc[8][4] = {};
#pragma unroll
        for (int ks = 0; ks < 8; ks++) {
#pragma unroll
            for (int nb = 0; nb < 8; nb++) {
                uint32_t b0 = __float_as_uint(Ks[(8 * nb + gID) * 68 + 8 * ks + tig]);
                uint32_t b1 = __float_as_uint(Ks[(8 * nb + gID) * 68 + 8 * ks + tig + 4]);
                mma_tf32(sacc[nb], qa[ks][0], qa[ks][1], qa[ks][2], qa[ks][3], b0, b1);
            }
        }

        // ---- online softmax (warp-local; quad reduction over tig) ----
        float mx0 = -1e30f, mx1 = -1e30f;
#pragma unroll
        for (int nb = 0; nb < 8; nb++) {
            mx0 = fmaxf(mx0, fmaxf(sacc[nb][0], sacc[nb][1]));
            mx1 = fmaxf(mx1, fmaxf(sacc[nb][2], sacc[nb][3]));
        }
        mx0 = fmaxf(mx0, __shfl_xor_sync(0xffffffffu, mx0, 1));
        mx0 = fmaxf(mx0, __shfl_xor_sync(0xffffffffu, mx0, 2));
        mx1 = fmaxf(mx1, __shfl_xor_sync(0xffffffffu, mx1, 1));
        mx1 = fmaxf(mx1, __shfl_xor_sync(0xffffffffu, mx1, 2));

        float nm0 = fmaxf(m0r, mx0);
        float nm1 = fmaxf(m1r, mx1);
        float c0 = __expf(m0r - nm0);
        float c1 = __expf(m1r - nm1);
        m0r = nm0; m1r = nm1;

        uint32_t pf[8][4];
        float s0 = 0.f, s1 = 0.f;
#pragma unroll
        for (int nb = 0; nb < 8; nb++) {
            pf[nb][0] = f2tf(__expf(sacc[nb][0] - nm0));
            pf[nb][1] = f2tf(__expf(sacc[nb][1] - nm0));
            pf[nb][2] = f2tf(__expf(sacc[nb][2] - nm1));
            pf[nb][3] = f2tf(__expf(sacc[nb][3] - nm1));
            s0 += __uint_as_float(pf[nb][0]) + __uint_as_float(pf[nb][1]);
            s1 += __uint_as_float(pf[nb][2]) + __uint_as_float(pf[nb][3]);
        }
        s0 += __shfl_xor_sync(0xffffffffu, s0, 1);
        s0 += __shfl_xor_sync(0xffffffffu, s0, 2);
        s1 += __shfl_xor_sync(0xffffffffu, s1, 1);
        s1 += __shfl_xor_sync(0xffffffffu, s1, 2);
        l0 = l0 * c0 + s0;
        l1 = l1 * c1 + s1;
#pragma unroll
        for (int nb = 0; nb < 8; nb++) {
            oacc[nb][0] *= c0; oacc[nb][1] *= c0;
            oacc[nb][2] *= c1; oacc[nb][3] *= c1;
        }

        // ---- O += P @ V  (P C-frag -> A-frag via quad shuffles) ----
#pragma unroll
        for (int ks = 0; ks < 8; ks++) {
            int base = lane & ~3;
            int s1i = base + (tig >> 1);
            int s2i = s1i + 2;
            uint32_t v00 = __shfl_sync(0xffffffffu, pf[ks][0], s1i);
            uint32_t v01 = __shfl_sync(0xffffffffu, pf[ks][1], s1i);
            uint32_t v10 = __shfl_sync(0xffffffffu, pf[ks][2], s1i);
            uint32_t v11 = __shfl_sync(0xffffffffu, pf[ks][3], s1i);
            uint32_t w00 = __shfl_sync(0xffffffffu, pf[ks][0], s2i);
            uint32_t w01 = __shfl_sync(0xffffffffu, pf[ks][1], s2i);
            uint32_t w10 = __shfl_sync(0xffffffffu, pf[ks][2], s2i);
            uint32_t w11 = __shfl_sync(0xffffffffu, pf[ks][3], s2i);
            uint32_t pa0 = (tig & 1) ? v01 : v00;   // row gID,   key 8ks+tig
            uint32_t pa1 = (tig & 1) ? v11 : v10;   // row gID+8, key 8ks+tig
            uint32_t pa2 = (tig & 1) ? w01 : w00;   // row gID,   key 8ks+tig+4
            uint32_t pa3 = (tig & 1) ? w11 : w10;   // row gID+8, key 8ks+tig+4
#pragma unroll
            for (int nb = 0; nb < 8; nb++) {
                uint32_t b0 = __float_as_uint(Vs[(8 * ks + tig)     * 72 + 8 * nb + gID]);
                uint32_t b1 = __float_as_uint(Vs[(8 * ks + tig + 4) * 72 + 8 * nb + gID]);
                mma_tf32(oacc[nb], pa0, pa1, pa2, pa3, b0, b1);
            }
        }
    }

    // ---- normalize + write ctx (b,s,d) ----
    int b = bh >> 3, h = bh & 7;
    float inv0 = 1.0f / l0;
    float inv1 = 1.0f / l1;
#pragma unroll
    for (int nb = 0; nb < 8; nb++) {
        int dv = 8 * nb + 2 * tig;
        long row0 = (long)b * SS + m0 + m0w + gID;
        long row1 = row0 + 8;
        *(float2*)&g_ctx[row0 * DD + h * HDD + dv] =
            make_float2(oacc[nb][0] * inv0, oacc[nb][1] * inv0);
        *(float2*)&g_ctx[row1 * DD + h * HDD + dv] =
            make_float2(oacc[nb][2] * inv1, oacc[nb][3] * inv1);
    }
}

// ---------------- launch ----------------
extern "C" void kernel_launch(void* const* d_in, const int* in_sizes, int n_in,
                              void* d_out, int out_size) {
    const float* x   = (const float*)d_in[0];
    const float* eps = (const float*)d_in[1];
    const float* wq  = (const float*)d_in[2];  const float* bq  = (const float*)d_in[3];
    const float* wk  = (const float*)d_in[4];  const float* bk  = (const float*)d_in[5];
    const float* wv  = (const float*)d_in[6];  const float* bv  = (const float*)d_in[7];
    const float* wo  = (const float*)d_in[8];  const float* bo  = (const float*)d_in[9];
    const float* we1 = (const float*)d_in[10]; const float* be1 = (const float*)d_in[11];
    const float* we2 = (const float*)d_in[12]; const float* be2 = (const float*)d_in[13];
    const float* wmu = (const float*)d_in[14]; const float* bmu = (const float*)d_in[15];
    const float* wlv = (const float*)d_in[16]; const float* blv = (const float*)d_in[17];
    const float* wf  = (const float*)d_in[18]; const float* bf  = (const float*)d_in[19];
    float* out = (float*)d_out;

    void *pq, *pk, *pv, *pctx;
    cudaGetSymbolAddress(&pq,  g_q);
    cudaGetSymbolAddress(&pk,  g_k);
    cudaGetSymbolAddress(&pv,  g_v);
    cudaGetSymbolAddress(&pctx, g_ctx);

    const int GEMM_SMEM  = (128 * 68 + 64 * 68) * 4;            // 52224
    const int FLASH_SMEM = (128 * 68 + 64 * 68 + 64 * 72) * 4;  // 70656
    cudaFuncSetAttribute(gemm_tc<true,  true >, cudaFuncAttributeMaxDynamicSharedMemorySize, GEMM_SMEM);
    cudaFuncSetAttribute(gemm_tc<false, true >, cudaFuncAttributeMaxDynamicSharedMemorySize, GEMM_SMEM);
    cudaFuncSetAttribute(gemm_tc<false, false>, cudaFuncAttributeMaxDynamicSharedMemorySize, GEMM_SMEM);
    cudaFuncSetAttribute(flash_tc, cudaFuncAttributeMaxDynamicSharedMemorySize, FLASH_SMEM);

    // 1) mean partials + 2) VAE MLP (writes mu/logvar tail + g_lat)
    mean_partial<<<BB * 32, DD>>>(x);
    vae_kernel<<<BB, DD>>>(eps, we1, be1, we2, be2, wmu, bmu, wlv, blv, wf, bf, out);

    // 3) projections (tf32 tensor cores)
    dim3 gg((BB * SS) / 128, DD / 64);
    gemm_tc<true,  true ><<<gg, 256, GEMM_SMEM>>>(x, wq, bq, (float*)pq);
    gemm_tc<true,  true ><<<gg, 256, GEMM_SMEM>>>(x, wk, bk, (float*)pk);
    gemm_tc<false, true ><<<gg, 256, GEMM_SMEM>>>(x, wv, bv, (float*)pv);

    // 4) attention (tf32 tensor cores)
    flash_tc<<<dim3(SS / 128, BB * HH), 256, FLASH_SMEM>>>();

    // 5) output projection -> d_out[0 .. B*S*D)
    gemm_tc<false, false><<<gg, 256, GEMM_SMEM>>>((float*)pctx, wo, bo, out);
}

// round 3
// speedup vs baseline: 1.8973x; 1.0132x over previous
#include <cuda_runtime.h>
#include <math.h>
#include <stdint.h>

#define BB   2
#define SS   4096
#define DD   512
#define HH   8
#define HDD  64
#define LAT  64

// ---------------- scratch (static device globals; no allocs) ----------------
__device__ float g_part[BB * 32 * DD];
__device__ float g_lat [BB * DD];
__device__ float g_q   [BB * HH * SS * HDD];    // (b,h,s,hd)
__device__ float g_k   [BB * HH * SS * HDD];
__device__ float g_v   [BB * HH * SS * HDD];
__device__ float g_ctx [BB * SS * DD];          // (b,s,d)

// ---------------- helpers ----------------
__device__ __forceinline__ uint32_t f2tf(float f) {
    uint32_t r;
    asm("cvt.rna.tf32.f32 %0, %1;" : "=r"(r) : "f"(f));
    return r;
}
__device__ __forceinline__ float u2f(uint32_t u) { return __uint_as_float(u); }

__device__ __forceinline__ void mma_tf32(float* c, uint32_t a0, uint32_t a1,
                                         uint32_t a2, uint32_t a3,
                                         uint32_t b0, uint32_t b1) {
    asm volatile(
        "mma.sync.aligned.m16n8k8.row.col.f32.tf32.tf32.f32 "
        "{%0,%1,%2,%3}, {%4,%5,%6,%7}, {%8,%9}, {%0,%1,%2,%3};\n"
        : "+f"(c[0]), "+f"(c[1]), "+f"(c[2]), "+f"(c[3])
        : "r"(a0), "r"(a1), "r"(a2), "r"(a3), "r"(b0), "r"(b1));
}

// ---------------- 1) mean over sequence: partial sums ----------------
__global__ void mean_partial(const float* __restrict__ x) {
    int bx = blockIdx.x;
    int b  = bx >> 5;
    int sp = bx & 31;
    int t  = threadIdx.x;           // 512
    const int chunk = SS / 32;
    const float* p = x + ((long)b * SS + (long)sp * chunk) * DD + t;
    float s = 0.f;
#pragma unroll 4
    for (int i = 0; i < chunk; i++) s += p[(long)i * DD];
    g_part[(long)bx * DD + t] = s;
}

// ---------------- 2) VAE MLP ----------------
__global__ void vae_kernel(const float* __restrict__ eps,
                           const float* __restrict__ we1, const float* __restrict__ be1,
                           const float* __restrict__ we2, const float* __restrict__ be2,
                           const float* __restrict__ wmu, const float* __restrict__ bmu,
                           const float* __restrict__ wlv, const float* __restrict__ blv,
                           const float* __restrict__ wf,  const float* __restrict__ bf,
                           float* __restrict__ out) {
    int b = blockIdx.x;
    int t = threadIdx.x;            // 512
    __shared__ float xm[DD];
    __shared__ float h1[256];
    __shared__ float h2[128];
    __shared__ float z [LAT];

    float s = 0.f;
#pragma unroll
    for (int i = 0; i < 32; i++) s += g_part[((long)b * 32 + i) * DD + t];
    xm[t] = s * (1.0f / (float)SS);
    __syncthreads();

    if (t < 256) {
        float a = be1[t];
        const float* w = we1 + (long)t * DD;
#pragma unroll 8
        for (int k = 0; k < DD; k++) a += xm[k] * w[k];
        h1[t] = fmaxf(a, 0.f);
    }
    __syncthreads();

    if (t < 128) {
        float a = be2[t];
        const float* w = we2 + (long)t * 256;
#pragma unroll 8
        for (int k = 0; k < 256; k++) a += h1[k] * w[k];
        h2[t] = fmaxf(a, 0.f);
    }
    __syncthreads();

    if (t < LAT) {
        float mu = bmu[t], lv = blv[t];
        const float* w1 = wmu + (long)t * 128;
        const float* w2 = wlv + (long)t * 128;
#pragma unroll 8
        for (int k = 0; k < 128; k++) { mu += h2[k] * w1[k]; lv += h2[k] * w2[k]; }
        out[(long)BB * SS * DD + b * LAT + t]            = mu;
        out[(long)BB * SS * DD + BB * LAT + b * LAT + t] = lv;
        z[t] = mu + eps[b * LAT + t] * expf(0.5f * lv);
    }
    __syncthreads();

    {
        float a = bf[t];
        const float* w = wf + (long)t * LAT;
#pragma unroll
        for (int k = 0; k < LAT; k++) a += z[k] * w[k];
        g_lat[b * DD + t] = a;
    }
}

// ---------------- 3) tf32 GEMM with fragment-resident smem ------------------
// C = A @ W^T + bias (+latent). A:(8192,512) W:(512,512). CTA 128x64, 8 warps.
// Smem layout:
//   Af: [rb 0..7][ks 0..7] blocks, each 33 float4 (lane-indexed a0..a3, 1-f4 pad)
//   Wf: [nb 0..7][ks 0..7] blocks, each 33 float2 (lane-indexed b0,b1, 1-f2 pad)
#define AF_FLOATS (64 * 132)
#define WF_FLOATS (64 * 66)

template <bool ADD_LAT, bool BHSD>
__global__ __launch_bounds__(256) void gemm_tc(const float* __restrict__ A,
                                               const float* __restrict__ W,
                                               const float* __restrict__ bias,
                                               float* __restrict__ out) {
    extern __shared__ float sm[];
    float* Af = sm;
    float* Wf = sm + AF_FLOATS;

    int tid  = threadIdx.x;
    int lane = tid & 31;
    int wid  = tid >> 5;
    int gID  = lane >> 2;
    int tig  = lane & 3;
    int m0   = blockIdx.x * 128;
    int n0   = blockIdx.y * 64;

    // producer indices
    int rA   = tid >> 1;            // 0..127
    int cA   = (tid & 1) * 32;
    int rbA  = rA >> 4;
    int gA   = rA & 7;
    int rowhi = (rA & 15) >> 3;
    int rW   = tid >> 2;            // 0..63
    int cW   = (tid & 3) * 16;
    int nbW  = rW >> 3;
    int gW   = rW & 7;

    float acc[8][4] = {};

    for (int kc = 0; kc < DD; kc += 64) {
        __syncthreads();
        // ---- scatter A chunk into fragment layout ----
        {
            const float* Ap = A + (long)(m0 + rA) * DD + kc + cA;
#pragma unroll
            for (int i = 0; i < 8; i++) {
                int k0 = cA + i * 4;
                int ks = k0 >> 3;
                int colhi = (k0 & 4) ? 1 : 0;
                float4 v = *(const float4*)(Ap + i * 4);
                float* d = Af + (rbA * 8 + ks) * 132 + 16 * gA + rowhi + 2 * colhi;
                d[0]  = u2f(f2tf(v.x));
                d[4]  = u2f(f2tf(v.y));
                d[8]  = u2f(f2tf(v.z));
                d[12] = u2f(f2tf(v.w));
            }
        }
        // ---- scatter W chunk ----
        {
            const float* Wp = W + (long)(n0 + rW) * DD + kc + cW;
#pragma unroll
            for (int i = 0; i < 4; i++) {
                int k0 = cW + i * 4;
                int ks = k0 >> 3;
                int pos = (k0 & 4) ? 1 : 0;
                float4 v = *(const float4*)(Wp + i * 4);
                float* d = Wf + ((nbW * 8 + ks) * 33 + 4 * gW) * 2 + pos;
                d[0] = u2f(f2tf(v.x));
                d[2] = u2f(f2tf(v.y));
                d[4] = u2f(f2tf(v.z));
                d[6] = u2f(f2tf(v.w));
            }
        }
        __syncthreads();

#pragma unroll
        for (int ks = 0; ks < 8; ks++) {
            float4 av = *(const float4*)&Af[(wid * 8 + ks) * 132 + lane * 4];
            uint32_t a0 = __float_as_uint(av.x);
            uint32_t a1 = __float_as_uint(av.y);
            uint32_t a2 = __float_as_uint(av.z);
            uint32_t a3 = __float_as_uint(av.w);
#pragma unroll
            for (int nb = 0; nb < 8; nb++) {
                float2 bv = *(const float2*)&Wf[((nb * 8 + ks) * 33 + lane) * 2];
                mma_tf32(acc[nb], a0, a1, a2, a3,
                         __float_as_uint(bv.x), __float_as_uint(bv.y));
            }
        }
    }

    // epilogue
    int m0w = wid * 16;
#pragma unroll
    for (int nb = 0; nb < 8; nb++) {
        int col = n0 + 8 * nb + 2 * tig;
        float bz0 = bias[col], bz1 = bias[col + 1];
#pragma unroll
        for (int rr = 0; rr < 2; rr++) {
            int row = m0 + m0w + gID + 8 * rr;
            int b = row >> 12;
            int sidx = row & 4095;
            float v0 = acc[nb][2 * rr + 0] + bz0;
            float v1 = acc[nb][2 * rr + 1] + bz1;
            if (ADD_LAT) {
                v0 += g_lat[b * DD + col];
                v1 += g_lat[b * DD + col + 1];
            }
            float2 o = make_float2(v0, v1);
            if (BHSD) {
                int h  = col >> 6;
                int hd = col & 63;
                *(float2*)&out[(((long)(b * HH + h) * SS + sidx) * HDD) + hd] = o;
            } else {
                *(float2*)&out[(long)row * DD + col] = o;
            }
        }
    }
}

// ---------------- 4) tf32 flash attention, fragment-resident smem -----------
// 128 q x 64 k tiles. 8 warps, warp = 16-row strip.
//   Kf: [nb][ks] blocks of 33 float2 (lane b0,b1)     (16.9 KB)
//   Vf: [ks][nb] blocks of 33 float2 (lane b0,b1)     (16.9 KB)
//   Q staged natural [128][68] in same smem before the loop (34.8 KB)
#define KF_FLOATS (64 * 66)
#define FLASH_SMEM_BYTES (128 * 68 * 4)   // 34816, covers Kf+Vf (33792)

__global__ __launch_bounds__(256, 2) void flash_tc() {
    extern __shared__ float sm[];
    float* Kf = sm;
    float* Vf = sm + KF_FLOATS;

    int tid  = threadIdx.x;
    int lane = tid & 31;
    int wid  = tid >> 5;
    int gID  = lane >> 2;
    int tig  = lane & 3;
    int bh   = blockIdx.y;
    int m0   = blockIdx.x * 128;
    int m0w  = wid * 16;

    const float* Qg = g_q + ((long)bh * SS + m0) * HDD;
    const float* Kg = g_k + (long)bh * SS * HDD;
    const float* Vg = g_v + (long)bh * SS * HDD;

    // ---- stage Q natural, then preload fragments (scale 1/8 folded in) ----
    {
        int r = tid >> 1, c = (tid & 1) * 32;
        const float* Qp = Qg + (long)r * HDD + c;
        float* Qd = sm + r * 68 + c;
#pragma unroll
        for (int i = 0; i < 8; i++) {
            float4 v = *(const float4*)(Qp + i * 4);
            Qd[i * 4 + 0] = u2f(f2tf(v.x * 0.125f));
            Qd[i * 4 + 1] = u2f(f2tf(v.y * 0.125f));
            Qd[i * 4 + 2] = u2f(f2tf(v.z * 0.125f));
            Qd[i * 4 + 3] = u2f(f2tf(v.w * 0.125f));
        }
    }
    __syncthreads();

    uint32_t qa[8][4];
#pragma unroll
    for (int ks = 0; ks < 8; ks++) {
        qa[ks][0] = __float_as_uint(sm[(m0w + gID)     * 68 + 8 * ks + tig]);
        qa[ks][1] = __float_as_uint(sm[(m0w + gID + 8) * 68 + 8 * ks + tig]);
        qa[ks][2] = __float_as_uint(sm[(m0w + gID)     * 68 + 8 * ks + tig + 4]);
        qa[ks][3] = __float_as_uint(sm[(m0w + gID + 8) * 68 + 8 * ks + tig + 4]);
    }

    // producer indices
    int rP   = tid >> 2;            // 0..63  (key row)
    int cP   = (tid & 3) * 16;
    int nbK  = rP >> 3;
    int gK   = rP & 7;
    int posV = (rP & 4) ? 1 : 0;
    int tigV = rP & 3;

    float oacc[8][4] = {};
    float m0r = -1e30f, m1r = -1e30f;
    float l0 = 0.f, l1 = 0.f;

    for (int n0 = 0; n0 < SS; n0 += 64) {
        __syncthreads();   // prior reads (incl. Q preload on iter 0) done
        // ---- scatter K, V tiles into fragment layout ----
        {
            const float* Kp = Kg + (long)(n0 + rP) * HDD + cP;
            const float* Vp = Vg + (long)(n0 + rP) * HDD + cP;
#pragma unroll
            for (int i = 0; i < 4; i++) {
                int k0 = cP + i * 4;
                int ks = k0 >> 3;
                int pos = (k0 & 4) ? 1 : 0;
                float4 kv = *(const float4*)(Kp + i * 4);
                float* dk = Kf + ((nbK * 8 + ks) * 33 + 4 * gK) * 2 + pos;
                dk[0] = u2f(f2tf(kv.x));
                dk[2] = u2f(f2tf(kv.y));
                dk[4] = u2f(f2tf(kv.z));
                dk[6] = u2f(f2tf(kv.w));
                float4 vv = *(const float4*)(Vp + i * 4);
                int g40 = (k0 & 4) * 4;     // 4*gV0, 0 or 16
                float* dv = Vf + ((nbK * 8 + ks) * 33 + g40 + tigV) * 2 + posV;
                dv[0]  = u2f(f2tf(vv.x));
                dv[8]  = u2f(f2tf(vv.y));
                dv[16] = u2f(f2tf(vv.z));
                dv[24] = u2f(f2tf(vv.w));
            }
        }
        __syncthreads();

        // ---- S = Q @ K^T ----
        float sacc[8][4] = {};
#pragma unroll
        for (int ks = 0; ks < 8; ks++) {
#pragma unroll
            for (int nb = 0; nb < 8; nb++) {
                float2 bv = *(const float2*)&Kf[((nb * 8 + ks) * 33 + lane) * 2];
                mma_tf32(sacc[nb], qa[ks][0], qa[ks][1], qa[ks][2], qa[ks][3],
                         __float_as_uint(bv.x), __float_as_uint(bv.y));
            }
        }

        // ---- online softmax (warp-local quad reduction) ----
        float mx0 = -1e30f, mx1 = -1e30f;
#pragma unroll
        for (int nb = 0; nb < 8; nb++) {
            mx0 = fmaxf(mx0, fmaxf(sacc[nb][0], sacc[nb][1]));
            mx1 = fmaxf(mx1, fmaxf(sacc[nb][2], sacc[nb][3]));
        }
        mx0 = fmaxf(mx0, __shfl_xor_sync(0xffffffffu, mx0, 1));
        mx0 = fmaxf(mx0, __shfl_xor_sync(0xffffffffu, mx0, 2));
        mx1 = fmaxf(mx1, __shfl_xor_sync(0xffffffffu, mx1, 1));
        mx1 = fmaxf(mx1, __shfl_xor_sync(0xffffffffu, mx1, 2));

        float nm0 = fmaxf(m0r, mx0);
        float nm1 = fmaxf(m1r, mx1);
        float c0 = __expf(m0r - nm0);
        float c1 = __expf(m1r - nm1);
        m0r = nm0; m1r = nm1;

        uint32_t pf[8][4];
        float s0 = 0.f, s1 = 0.f;
#pragma unroll
        for (int nb = 0; nb < 8; nb++) {
            pf[nb][0] = f2tf(__expf(sacc[nb][0] - nm0));
            pf[nb][1] = f2tf(__expf(sacc[nb][1] - nm0));
            pf[nb][2] = f2tf(__expf(sacc[nb][2] - nm1));
            pf[nb][3] = f2tf(__expf(sacc[nb][3] - nm1));
            s0 += u2f(pf[nb][0]) + u2f(pf[nb][1]);
            s1 += u2f(pf[nb][2]) + u2f(pf[nb][3]);
        }
        s0 += __shfl_xor_sync(0xffffffffu, s0, 1);
        s0 += __shfl_xor_sync(0xffffffffu, s0, 2);
        s1 += __shfl_xor_sync(0xffffffffu, s1, 1);
        s1 += __shfl_xor_sync(0xffffffffu, s1, 2);
        l0 = l0 * c0 + s0;
        l1 = l1 * c1 + s1;
#pragma unroll
        for (int nb = 0; nb < 8; nb++) {
            oacc[nb][0] *= c0; oacc[nb][1] *= c0;
            oacc[nb][2] *= c1; oacc[nb][3] *= c1;
        }

        // ---- O += P @ V  (P C-frag -> A-frag via quad shuffles) ----
#pragma unroll
        for (int ks = 0; ks < 8; ks++) {
            int base = lane & ~3;
            int s1i = base + (tig >> 1);
            int s2i = s1i + 2;
            uint32_t v00 = __shfl_sync(0xffffffffu, pf[ks][0], s1i);
            uint32_t v01 = __shfl_sync(0xffffffffu, pf[ks][1], s1i);
            uint32_t v10 = __shfl_sync(0xffffffffu, pf[ks][2], s1i);
            uint32_t v11 = __shfl_sync(0xffffffffu, pf[ks][3], s1i);
            uint32_t w00 = __shfl_sync(0xffffffffu, pf[ks][0], s2i);
            uint32_t w01 = __shfl_sync(0xffffffffu, pf[ks][1], s2i);
            uint32_t w10 = __shfl_sync(0xffffffffu, pf[ks][2], s2i);
            uint32_t w11 = __shfl_sync(0xffffffffu, pf[ks][3], s2i);
            uint32_t pa0 = (tig & 1) ? v01 : v00;
            uint32_t pa1 = (tig & 1) ? v11 : v10;
            uint32_t pa2 = (tig & 1) ? w01 : w00;
            uint32_t pa3 = (tig & 1) ? w11 : w10;
#pragma unroll
            for (int nb = 0; nb < 8; nb++) {
                float2 bv = *(const float2*)&Vf[((ks * 8 + nb) * 33 + lane) * 2];
                mma_tf32(oacc[nb], pa0, pa1, pa2, pa3,
                         __float_as_uint(bv.x), __float_as_uint(bv.y));
            }
        }
    }

    // ---- normalize + write ctx (b,s,d) ----
    int b = bh >> 3, h = bh & 7;
    float inv0 = 1.0f / l0;
    float inv1 = 1.0f / l1;
#pragma unroll
    for (int nb = 0; nb < 8; nb++) {
        int dv = 8 * nb + 2 * tig;
        long row0 = (long)b * SS + m0 + m0w + gID;
        long row1 = row0 + 8;
        *(float2*)&g_ctx[row0 * DD + h * HDD + dv] =
            make_float2(oacc[nb][0] * inv0, oacc[nb][1] * inv0);
        *(float2*)&g_ctx[row1 * DD + h * HDD + dv] =
            make_float2(oacc[nb][2] * inv1, oacc[nb][3] * inv1);
    }
}

// ---------------- launch ----------------
extern "C" void kernel_launch(void* const* d_in, const int* in_sizes, int n_in,
                              void* d_out, int out_size) {
    const float* x   = (const float*)d_in[0];
    const float* eps = (const float*)d_in[1];
    const float* wq  = (const float*)d_in[2];  const float* bq  = (const float*)d_in[3];
    const float* wk  = (const float*)d_in[4];  const float* bk  = (const float*)d_in[5];
    const float* wv  = (const float*)d_in[6];  const float* bv  = (const float*)d_in[7];
    const float* wo  = (const float*)d_in[8];  const float* bo  = (const float*)d_in[9];
    const float* we1 = (const float*)d_in[10]; const float* be1 = (const float*)d_in[11];
    const float* we2 = (const float*)d_in[12]; const float* be2 = (const float*)d_in[13];
    const float* wmu = (const float*)d_in[14]; const float* bmu = (const float*)d_in[15];
    const float* wlv = (const float*)d_in[16]; const float* blv = (const float*)d_in[17];
    const float* wf  = (const float*)d_in[18]; const float* bf  = (const float*)d_in[19];
    float* out = (float*)d_out;

    void *pq, *pk, *pv, *pctx;
    cudaGetSymbolAddress(&pq,  g_q);
    cudaGetSymbolAddress(&pk,  g_k);
    cudaGetSymbolAddress(&pv,  g_v);
    cudaGetSymbolAddress(&pctx, g_ctx);

    const int GEMM_SMEM = (AF_FLOATS + WF_FLOATS) * 4;    // 50688
    cudaFuncSetAttribute(gemm_tc<true,  true >, cudaFuncAttributeMaxDynamicSharedMemorySize, GEMM_SMEM);
    cudaFuncSetAttribute(gemm_tc<false, true >, cudaFuncAttributeMaxDynamicSharedMemorySize, GEMM_SMEM);
    cudaFuncSetAttribute(gemm_tc<false, false>, cudaFuncAttributeMaxDynamicSharedMemorySize, GEMM_SMEM);
    cudaFuncSetAttribute(flash_tc, cudaFuncAttributeMaxDynamicSharedMemorySize, FLASH_SMEM_BYTES);

    mean_partial<<<BB * 32, DD>>>(x);
    vae_kernel<<<BB, DD>>>(eps, we1, be1, we2, be2, wmu, bmu, wlv, blv, wf, bf, out);

    dim3 gg((BB * SS) / 128, DD / 64);
    gemm_tc<true,  true ><<<gg, 256, GEMM_SMEM>>>(x, wq, bq, (float*)pq);
    gemm_tc<true,  true ><<<gg, 256, GEMM_SMEM>>>(x, wk, bk, (float*)pk);
    gemm_tc<false, true ><<<gg, 256, GEMM_SMEM>>>(x, wv, bv, (float*)pv);

    flash_tc<<<dim3(SS / 128, BB * HH), 256, FLASH_SMEM_BYTES>>>();

    gemm_tc<false, false><<<gg, 256, GEMM_SMEM>>>((float*)pctx, wo, bo, out);
}

// round 5
// speedup vs baseline: 2.7150x; 1.4310x over previous
#include <cuda_runtime.h>
#include <math.h>
#include <stdint.h>

#define BB   2
#define SS   4096
#define DD   512
#define HH   8
#define HDD  64
#define LAT  64

// ---------------- scratch (static device globals; no allocs) ----------------
__device__ float g_part[BB * 32 * DD];
__device__ float g_lat [BB * DD];
__device__ float g_q   [BB * HH * SS * HDD];    // (b,h,s,hd)
__device__ float g_k   [BB * HH * SS * HDD];
__device__ float g_v   [BB * HH * SS * HDD];
__device__ float g_ctx [BB * SS * DD];          // (b,s,d)

// ---------------- helpers ----------------
__device__ __forceinline__ uint32_t f2tf(float f) {
    uint32_t r;
    asm("cvt.rna.tf32.f32 %0, %1;" : "=r"(r) : "f"(f));
    return r;
}
__device__ __forceinline__ uint32_t cvt_raw(uint32_t raw) {
    return f2tf(__uint_as_float(raw));
}
__device__ __forceinline__ float u2f(uint32_t u) { return __uint_as_float(u); }

__device__ __forceinline__ void mma_tf32(float* c, uint32_t a0, uint32_t a1,
                                         uint32_t a2, uint32_t a3,
                                         uint32_t b0, uint32_t b1) {
    asm volatile(
        "mma.sync.aligned.m16n8k8.row.col.f32.tf32.tf32.f32 "
        "{%0,%1,%2,%3}, {%4,%5,%6,%7}, {%8,%9}, {%0,%1,%2,%3};\n"
        : "+f"(c[0]), "+f"(c[1]), "+f"(c[2]), "+f"(c[3])
        : "r"(a0), "r"(a1), "r"(a2), "r"(a3), "r"(b0), "r"(b1));
}

__device__ __forceinline__ void ldsm4(uint32_t addr, uint32_t& r0, uint32_t& r1,
                                      uint32_t& r2, uint32_t& r3) {
    asm volatile("ldmatrix.sync.aligned.m8n8.x4.shared.b16 {%0,%1,%2,%3}, [%4];\n"
                 : "=r"(r0), "=r"(r1), "=r"(r2), "=r"(r3) : "r"(addr));
}

#define CP_A16(dst, src) \
    asm volatile("cp.async.ca.shared.global [%0], [%1], 16;\n" :: "r"(dst), "l"(src))
#define CP_COMMIT() asm volatile("cp.async.commit_group;\n" ::: "memory")
#define CP_WAIT(n)  asm volatile("cp.async.wait_group %0;\n" :: "n"(n) : "memory")

// ---------------- 1) mean over sequence: partial sums ----------------
__global__ void mean_partial(const float* __restrict__ x) {
    int bx = blockIdx.x;
    int b  = bx >> 5;
    int sp = bx & 31;
    int t  = threadIdx.x;           // 512
    const int chunk = SS / 32;
    const float* p = x + ((long)b * SS + (long)sp * chunk) * DD + t;
    float s = 0.f;
#pragma unroll 4
    for (int i = 0; i < chunk; i++) s += p[(long)i * DD];
    g_part[(long)bx * DD + t] = s;
}

// ---------------- 2) VAE MLP ----------------
__global__ void vae_kernel(const float* __restrict__ eps,
                           const float* __restrict__ we1, const float* __restrict__ be1,
                           const float* __restrict__ we2, const float* __restrict__ be2,
                           const float* __restrict__ wmu, const float* __restrict__ bmu,
                           const float* __restrict__ wlv, const float* __restrict__ blv,
                           const float* __restrict__ wf,  const float* __restrict__ bf,
                           float* __restrict__ out) {
    int b = blockIdx.x;
    int t = threadIdx.x;            // 512
    __shared__ float xm[DD];
    __shared__ float h1[256];
    __shared__ float h2[128];
    __shared__ float z [LAT];

    float s = 0.f;
#pragma unroll
    for (int i = 0; i < 32; i++) s += g_part[((long)b * 32 + i) * DD + t];
    xm[t] = s * (1.0f / (float)SS);
    __syncthreads();

    if (t < 256) {
        float a = be1[t];
        const float* w = we1 + (long)t * DD;
#pragma unroll 8
        for (int k = 0; k < DD; k++) a += xm[k] * w[k];
        h1[t] = fmaxf(a, 0.f);
    }
    __syncthreads();

    if (t < 128) {
        float a = be2[t];
        const float* w = we2 + (long)t * 256;
#pragma unroll 8
        for (int k = 0; k < 256; k++) a += h1[k] * w[k];
        h2[t] = fmaxf(a, 0.f);
    }
    __syncthreads();

    if (t < LAT) {
        float mu = bmu[t], lv = blv[t];
        const float* w1 = wmu + (long)t * 128;
        const float* w2 = wlv + (long)t * 128;
#pragma unroll 8
        for (int k = 0; k < 128; k++) { mu += h2[k] * w1[k]; lv += h2[k] * w2[k]; }
        out[(long)BB * SS * DD + b * LAT + t]            = mu;
        out[(long)BB * SS * DD + BB * LAT + b * LAT + t] = lv;
        z[t] = mu + eps[b * LAT + t] * expf(0.5f * lv);
    }
    __syncthreads();

    {
        float a = bf[t];
        const float* w = wf + (long)t * LAT;
#pragma unroll
        for (int k = 0; k < LAT; k++) a += z[k] * w[k];
        g_lat[b * DD + t] = a;
    }
}

// ---------------- 3) tf32 GEMM: cp.async 3-stage + ldmatrix ------------------
// C = A @ W^T + bias (+latent). CTA 128x128, 8 warps as 4(M) x 2(N),
// warp tile 32x64. k-chunk 16, rows padded to 20 floats (conflict-free ldsm).
#define G_CK      16
#define G_RS      20
#define G_STGF    (2 * 128 * G_RS)          // floats per stage (A+W)
#define G_STAGES  3
#define GEMM_SMEM_BYTES (G_STAGES * G_STGF * 4)   // 61440

template <bool ADD_LAT, bool BHSD>
__global__ __launch_bounds__(256, 2) void gemm_tc(const float* __restrict__ A,
                                                  const float* __restrict__ W,
                                                  const float* __restrict__ bias,
                                                  float* __restrict__ out) {
    extern __shared__ float sm[];
    uint32_t smb = (uint32_t)__cvta_generic_to_shared(sm);

    int tid  = threadIdx.x;
    int lane = tid & 31;
    int wid  = tid >> 5;
    int gID  = lane >> 2;
    int tig  = lane & 3;
    int wm   = wid & 3;             // 0..3, 32-row strip
    int wn   = wid >> 2;            // 0..1, 64-col strip
    int m0   = blockIdx.x * 128;
    int n0   = blockIdx.y * 128;

    int mtx = lane >> 3;            // ldmatrix sub-matrix id
    int lr  = lane & 7;

    // producer: seg = tid + i*256 (i=0,1); row = seg>>2, sc = seg&3
    int pr0 = tid >> 2, pc0 = (tid & 3) * 4;
    int pr1 = (tid + 256) >> 2, pc1 = ((tid + 256) & 3) * 4;

    auto prefetch = [&](int c, int st) {
        const float* Asrc = A + (long)(m0 + pr0) * DD + c * G_CK + pc0;
        const float* Wsrc = W + (long)(n0 + pr0) * DD + c * G_CK + pc0;
        uint32_t d0 = smb + (st * G_STGF + pr0 * G_RS + pc0) * 4;
        uint32_t d1 = smb + (st * G_STGF + 128 * G_RS + pr0 * G_RS + pc0) * 4;
        CP_A16(d0, Asrc);
        CP_A16(d1, Wsrc);
        const float* Asrc1 = A + (long)(m0 + pr1) * DD + c * G_CK + pc1;
        const float* Wsrc1 = W + (long)(n0 + pr1) * DD + c * G_CK + pc1;
        uint32_t d2 = smb + (st * G_STGF + pr1 * G_RS + pc1) * 4;
        uint32_t d3 = smb + (st * G_STGF + 128 * G_RS + pr1 * G_RS + pc1) * 4;
        CP_A16(d2, Asrc1);
        CP_A16(d3, Wsrc1);
    };

    // preload stages 0..1
    prefetch(0, 0); CP_COMMIT();
    prefetch(1, 1); CP_COMMIT();

    float acc[2][8][4] = {};

    // per-lane ldmatrix base offsets (floats)
    int rowA0 = wm * 32 + (mtx & 1) * 8 + lr;     // mt adds 16
    int colA  = (mtx >> 1) * 4;
    int rowB0 = wn * 64 + (mtx >> 1) * 8 + lr;    // nbp adds 16
    int colB  = (mtx & 1) * 4;

    const int NCH = DD / G_CK;    // 32
    for (int c = 0; c < NCH; c++) {
        CP_WAIT(1);
        __syncthreads();
        if (c + 2 < NCH) prefetch(c + 2, (c + 2) % G_STAGES);
        CP_COMMIT();

        uint32_t stA = smb + ((c % G_STAGES) * G_STGF) * 4;
        uint32_t stW = stA + 128 * G_RS * 4;

#pragma unroll
        for (int ks = 0; ks < 2; ks++) {
            uint32_t a[2][4];
#pragma unroll
            for (int mt = 0; mt < 2; mt++) {
                ldsm4(stA + ((rowA0 + mt * 16) * G_RS + 8 * ks + colA) * 4,
                      a[mt][0], a[mt][1], a[mt][2], a[mt][3]);
            }
            uint32_t b[8][2];
#pragma unroll
            for (int nbp = 0; nbp < 4; nbp++) {
                ldsm4(stW + ((rowB0 + nbp * 16) * G_RS + 8 * ks + colB) * 4,
                      b[2 * nbp][0], b[2 * nbp][1], b[2 * nbp + 1][0], b[2 * nbp + 1][1]);
            }
#pragma unroll
            for (int mt = 0; mt < 2; mt++)
#pragma unroll
                for (int j = 0; j < 4; j++) a[mt][j] = cvt_raw(a[mt][j]);
#pragma unroll
            for (int nb = 0; nb < 8; nb++) {
                b[nb][0] = cvt_raw(b[nb][0]);
                b[nb][1] = cvt_raw(b[nb][1]);
            }
#pragma unroll
            for (int mt = 0; mt < 2; mt++)
#pragma unroll
                for (int nb = 0; nb < 8; nb++)
                    mma_tf32(acc[mt][nb], a[mt][0], a[mt][1], a[mt][2], a[mt][3],
                             b[nb][0], b[nb][1]);
        }
    }

    // epilogue
#pragma unroll
    for (int mt = 0; mt < 2; mt++) {
#pragma unroll
        for (int nb = 0; nb < 8; nb++) {
            int col = n0 + wn * 64 + nb * 8 + 2 * tig;
            float bz0 = bias[col], bz1 = bias[col + 1];
#pragma unroll
            for (int rr = 0; rr < 2; rr++) {
                int row = m0 + wm * 32 + mt * 16 + gID + 8 * rr;
                int b = row >> 12;
                int sidx = row & 4095;
                float v0 = acc[mt][nb][2 * rr + 0] + bz0;
                float v1 = acc[mt][nb][2 * rr + 1] + bz1;
                if (ADD_LAT) {
                    v0 += g_lat[b * DD + col];
                    v1 += g_lat[b * DD + col + 1];
                }
                float2 o = make_float2(v0, v1);
                if (BHSD) {
                    int h  = col >> 6;
                    int hd = col & 63;
                    *(float2*)&out[(((long)(b * HH + h) * SS + sidx) * HDD) + hd] = o;
                } else {
                    *(float2*)&out[(long)row * DD + col] = o;
                }
            }
        }
    }
}

// ---------------- 4) tf32 flash attention: cp.async 2-stage + ldmatrix ------
// 128 q x 64 k tiles. 8 warps, warp = 16-row strip. Q frags from global.
// K smem [64][68] (ldsm conflict-free), V smem [64][72] (scalar LDS, cf).
#define F_KST (64 * 68)
#define F_VST (64 * 72)
#define FLASH_SMEM_BYTES ((2 * F_KST + 2 * F_VST) * 4)   // 71680

__global__ __launch_bounds__(256, 2) void flash_tc() {
    extern __shared__ float sm[];
    uint32_t smb = (uint32_t)__cvta_generic_to_shared(sm);

    int tid  = threadIdx.x;
    int lane = tid & 31;
    int wid  = tid >> 5;
    int gID  = lane >> 2;
    int tig  = lane & 3;
    int bh   = blockIdx.y;
    int m0   = blockIdx.x * 128;
    int m0w  = wid * 16;

    int mtx = lane >> 3;
    int lr  = lane & 7;

    const float* Qg = g_q + ((long)bh * SS + m0) * HDD;
    const float* Kg = g_k + (long)bh * SS * HDD;
    const float* Vg = g_v + (long)bh * SS * HDD;

    // ---- Q fragments straight from global (scale 1/8 folded) ----
    uint32_t qa[8][4];
#pragma unroll
    for (int ks = 0; ks < 8; ks++) {
        qa[ks][0] = f2tf(Qg[(m0w + gID)     * HDD + 8 * ks + tig]     * 0.125f);
        qa[ks][1] = f2tf(Qg[(m0w + gID + 8) * HDD + 8 * ks + tig]     * 0.125f);
        qa[ks][2] = f2tf(Qg[(m0w + gID)     * HDD + 8 * ks + tig + 4] * 0.125f);
        qa[ks][3] = f2tf(Qg[(m0w + gID + 8) * HDD + 8 * ks + tig + 4] * 0.125f);
    }

    // producer: 4 K segs + 4 V segs per thread; seg = tid + i*256
    auto prefetch = [&](int c, int st) {
        long base = (long)c * 64 * HDD;
#pragma unroll
        for (int i = 0; i < 4; i++) {
            int s = tid + i * 256;
            int r = s >> 4, sc = (s & 15) * 4;
            CP_A16(smb + (st * F_KST + r * 68 + sc) * 4, Kg + base + r * HDD + sc);
            CP_A16(smb + (2 * F_KST + st * F_VST + r * 72 + sc) * 4, Vg + base + r * HDD + sc);
        }
    };

    prefetch(0, 0); CP_COMMIT();

    float oacc[8][4] = {};
    float m0r = -1e30f, m1r = -1e30f;
    float l0 = 0.f, l1 = 0.f;

    int rowK0 = (mtx >> 1) * 8 + lr;      // + nbp*16
    int colK  = (mtx & 1) * 4;

    const int NT = SS / 64;   // 64 tiles
    for (int c = 0; c < NT; c++) {
        CP_WAIT(0);
        __syncthreads();
        if (c + 1 < NT) prefetch(c + 1, (c + 1) & 1);
        CP_COMMIT();

        uint32_t stK = smb + ((c & 1) * F_KST) * 4;
        const float* Vsb = sm + 2 * F_KST + (c & 1) * F_VST;

        // ---- S = Q @ K^T ----
        float sacc[8][4] = {};
#pragma unroll
        for (int ks = 0; ks < 8; ks++) {
            uint32_t b[8][2];
#pragma unroll
            for (int nbp = 0; nbp < 4; nbp++) {
                ldsm4(stK + ((rowK0 + nbp * 16) * 68 + 8 * ks + colK) * 4,
                      b[2 * nbp][0], b[2 * nbp][1], b[2 * nbp + 1][0], b[2 * nbp + 1][1]);
            }
#pragma unroll
            for (int nb = 0; nb < 8; nb++) {
                b[nb][0] = cvt_raw(b[nb][0]);
                b[nb][1] = cvt_raw(b[nb][1]);
                mma_tf32(sacc[nb], qa[ks][0], qa[ks][1], qa[ks][2], qa[ks][3],
                         b[nb][0], b[nb][1]);
            }
        }

        // ---- online softmax (warp-local quad reduction) ----
        float mx0 = -1e30f, mx1 = -1e30f;
#pragma unroll
        for (int nb = 0; nb < 8; nb++) {
            mx0 = fmaxf(mx0, fmaxf(sacc[nb][0], sacc[nb][1]));
            mx1 = fmaxf(mx1, fmaxf(sacc[nb][2], sacc[nb][3]));
        }
        mx0 = fmaxf(mx0, __shfl_xor_sync(0xffffffffu, mx0, 1));
        mx0 = fmaxf(mx0, __shfl_xor_sync(0xffffffffu, mx0, 2));
        mx1 = fmaxf(mx1, __shfl_xor_sync(0xffffffffu, mx1, 1));
        mx1 = fmaxf(mx1, __shfl_xor_sync(0xffffffffu, mx1, 2));

        float nm0 = fmaxf(m0r, mx0);
        float nm1 = fmaxf(m1r, mx1);
        float c0 = __expf(m0r - nm0);
        float c1 = __expf(m1r - nm1);
        m0r = nm0; m1r = nm1;

        uint32_t pf[8][4];
        float s0 = 0.f, s1 = 0.f;
#pragma unroll
        for (int nb = 0; nb < 8; nb++) {
            pf[nb][0] = f2tf(__expf(sacc[nb][0] - nm0));
            pf[nb][1] = f2tf(__expf(sacc[nb][1] - nm0));
            pf[nb][2] = f2tf(__expf(sacc[nb][2] - nm1));
            pf[nb][3] = f2tf(__expf(sacc[nb][3] - nm1));
            s0 += u2f(pf[nb][0]) + u2f(pf[nb][1]);
            s1 += u2f(pf[nb][2]) + u2f(pf[nb][3]);
        }
        s0 += __shfl_xor_sync(0xffffffffu, s0, 1);
        s0 += __shfl_xor_sync(0xffffffffu, s0, 2);
        s1 += __shfl_xor_sync(0xffffffffu, s1, 1);
        s1 += __shfl_xor_sync(0xffffffffu, s1, 2);
        l0 = l0 * c0 + s0;
        l1 = l1 * c1 + s1;
#pragma unroll
        for (int nb = 0; nb < 8; nb++) {
            oacc[nb][0] *= c0; oacc[nb][1] *= c0;
            oacc[nb][2] *= c1; oacc[nb][3] *= c1;
        }

        // ---- O += P @ V ----
#pragma unroll
        for (int ks = 0; ks < 8; ks++) {
            int base = lane & ~3;
            int s1i = base + (tig >> 1);
            int s2i = s1i + 2;
            uint32_t v00 = __shfl_sync(0xffffffffu, pf[ks][0], s1i);
            uint32_t v01 = __shfl_sync(0xffffffffu, pf[ks][1], s1i);
            uint32_t v10 = __shfl_sync(0xffffffffu, pf[ks][2], s1i);
            uint32_t v11 = __shfl_sync(0xffffffffu, pf[ks][3], s1i);
            uint32_t w00 = __shfl_sync(0xffffffffu, pf[ks][0], s2i);
            uint32_t w01 = __shfl_sync(0xffffffffu, pf[ks][1], s2i);
            uint32_t w10 = __shfl_sync(0xffffffffu, pf[ks][2], s2i);
            uint32_t w11 = __shfl_sync(0xffffffffu, pf[ks][3], s2i);
            uint32_t pa0 = (tig & 1) ? v01 : v00;
            uint32_t pa1 = (tig & 1) ? v11 : v10;
            uint32_t pa2 = (tig & 1) ? w01 : w00;
            uint32_t pa3 = (tig & 1) ? w11 : w10;
#pragma unroll
            for (int nb = 0; nb < 8; nb++) {
                uint32_t b0 = f2tf(Vsb[(8 * ks + tig)     * 72 + 8 * nb + gID]);
                uint32_t b1 = f2tf(Vsb[(8 * ks + tig + 4) * 72 + 8 * nb + gID]);
                mma_tf32(oacc[nb], pa0, pa1, pa2, pa3, b0, b1);
            }
        }
    }

    // ---- normalize + write ctx (b,s,d) ----
    int b = bh >> 3, h = bh & 7;
    float inv0 = 1.0f / l0;
    float inv1 = 1.0f / l1;
#pragma unroll
    for (int nb = 0; nb < 8; nb++) {
        int dv = 8 * nb + 2 * tig;
        long row0 = (long)b * SS + m0 + m0w + gID;
        long row1 = row0 + 8;
        *(float2*)&g_ctx[row0 * DD + h * HDD + dv] =
            make_float2(oacc[nb][0] * inv0, oacc[nb][1] * inv0);
        *(float2*)&g_ctx[row1 * DD + h * HDD + dv] =
            make_float2(oacc[nb][2] * inv1, oacc[nb][3] * inv1);
    }
}

// ---------------- launch ----------------
extern "C" void kernel_launch(void* const* d_in, const int* in_sizes, int n_in,
                              void* d_out, int out_size) {
    const float* x   = (const float*)d_in[0];
    const float* eps = (const float*)d_in[1];
    const float* wq  = (const float*)d_in[2];  const float* bq  = (const float*)d_in[3];
    const float* wk  = (const float*)d_in[4];  const float* bk  = (const float*)d_in[5];
    const float* wv  = (const float*)d_in[6];  const float* bv  = (const float*)d_in[7];
    const float* wo  = (const float*)d_in[8];  const float* bo  = (const float*)d_in[9];
    const float* we1 = (const float*)d_in[10]; const float* be1 = (const float*)d_in[11];
    const float* we2 = (const float*)d_in[12]; const float* be2 = (const float*)d_in[13];
    const float* wmu = (const float*)d_in[14]; const float* bmu = (const float*)d_in[15];
    const float* wlv = (const float*)d_in[16]; const float* blv = (const float*)d_in[17];
    const float* wf  = (const float*)d_in[18]; const float* bf  = (const float*)d_in[19];
    float* out = (float*)d_out;

    void *pq, *pk, *pv, *pctx;
    cudaGetSymbolAddress(&pq,  g_q);
    cudaGetSymbolAddress(&pk,  g_k);
    cudaGetSymbolAddress(&pv,  g_v);
    cudaGetSymbolAddress(&pctx, g_ctx);

    cudaFuncSetAttribute(gemm_tc<true,  true >, cudaFuncAttributeMaxDynamicSharedMemorySize, GEMM_SMEM_BYTES);
    cudaFuncSetAttribute(gemm_tc<false, true >, cudaFuncAttributeMaxDynamicSharedMemorySize, GEMM_SMEM_BYTES);
    cudaFuncSetAttribute(gemm_tc<false, false>, cudaFuncAttributeMaxDynamicSharedMemorySize, GEMM_SMEM_BYTES);
    cudaFuncSetAttribute(flash_tc, cudaFuncAttributeMaxDynamicSharedMemorySize, FLASH_SMEM_BYTES);

    mean_partial<<<BB * 32, DD>>>(x);
    vae_kernel<<<BB, DD>>>(eps, we1, be1, we2, be2, wmu, bmu, wlv, blv, wf, bf, out);

    dim3 gg((BB * SS) / 128, DD / 128);
    gemm_tc<true,  true ><<<gg, 256, GEMM_SMEM_BYTES>>>(x, wq, bq, (float*)pq);
    gemm_tc<true,  true ><<<gg, 256, GEMM_SMEM_BYTES>>>(x, wk, bk, (float*)pk);
    gemm_tc<false, true ><<<gg, 256, GEMM_SMEM_BYTES>>>(x, wv, bv, (float*)pv);

    flash_tc<<<dim3(SS / 128, BB * HH), 256, FLASH_SMEM_BYTES>>>();

    gemm_tc<false, false><<<gg, 256, GEMM_SMEM_BYTES>>>((float*)pctx, wo, bo, out);
}

// round 7
// speedup vs baseline: 3.1345x; 1.1545x over previous
#include <cuda_runtime.h>
#include <math.h>
#include <stdint.h>

#define BB   2
#define SS   4096
#define DD   512
#define HH   8
#define HDD  64
#define LAT  64

// ---------------- scratch (static device globals; no allocs) ----------------
__device__ float g_part[BB * 32 * DD];
__device__ float g_lat [BB * DD];
__device__ float g_q   [BB * HH * SS * HDD];    // (b,h,s,hd)  tf32 bits, prescaled 1/8
__device__ float g_k   [BB * HH * SS * HDD];    // (b,h,s,hd)  tf32 bits
__device__ float g_v   [BB * HH * HDD * SS];    // (b,h,hd,s)  tf32 bits (TRANSPOSED)
__device__ float g_ctx [BB * SS * DD];          // (b,s,d)  fp32

// ---------------- helpers ----------------
__device__ __forceinline__ uint32_t f2tf(float f) {
    uint32_t r;
    asm("cvt.rna.tf32.f32 %0, %1;" : "=r"(r) : "f"(f));
    return r;
}
__device__ __forceinline__ uint32_t cvt_raw(uint32_t raw) {
    return f2tf(__uint_as_float(raw));
}
__device__ __forceinline__ float u2f(uint32_t u) { return __uint_as_float(u); }

__device__ __forceinline__ void mma_tf32(float* c, uint32_t a0, uint32_t a1,
                                         uint32_t a2, uint32_t a3,
                                         uint32_t b0, uint32_t b1) {
    asm volatile(
        "mma.sync.aligned.m16n8k8.row.col.f32.tf32.tf32.f32 "
        "{%0,%1,%2,%3}, {%4,%5,%6,%7}, {%8,%9}, {%0,%1,%2,%3};\n"
        : "+f"(c[0]), "+f"(c[1]), "+f"(c[2]), "+f"(c[3])
        : "r"(a0), "r"(a1), "r"(a2), "r"(a3), "r"(b0), "r"(b1));
}

__device__ __forceinline__ void ldsm4(uint32_t addr, uint32_t& r0, uint32_t& r1,
                                      uint32_t& r2, uint32_t& r3) {
    asm volatile("ldmatrix.sync.aligned.m8n8.x4.shared.b16 {%0,%1,%2,%3}, [%4];\n"
                 : "=r"(r0), "=r"(r1), "=r"(r2), "=r"(r3) : "r"(addr));
}

#define CP_A16(dst, src) \
    asm volatile("cp.async.ca.shared.global [%0], [%1], 16;\n" :: "r"(dst), "l"(src))
#define CP_COMMIT() asm volatile("cp.async.commit_group;\n" ::: "memory")
#define CP_WAIT(n)  asm volatile("cp.async.wait_group %0;\n" :: "n"(n) : "memory")

// ---------------- 1) mean over sequence: partial sums ----------------
__global__ void mean_partial(const float* __restrict__ x) {
    int bx = blockIdx.x;
    int b  = bx >> 5;
    int sp = bx & 31;
    int t  = threadIdx.x;           // 512
    const int chunk = SS / 32;
    const float* p = x + ((long)b * SS + (long)sp * chunk) * DD + t;
    float s = 0.f;
#pragma unroll 4
    for (int i = 0; i < chunk; i++) s += p[(long)i * DD];
    g_part[(long)bx * DD + t] = s;
}

// ---------------- 2) VAE MLP ----------------
__global__ void vae_kernel(const float* __restrict__ eps,
                           const float* __restrict__ we1, const float* __restrict__ be1,
                           const float* __restrict__ we2, const float* __restrict__ be2,
                           const float* __restrict__ wmu, const float* __restrict__ bmu,
                           const float* __restrict__ wlv, const float* __restrict__ blv,
                           const float* __restrict__ wf,  const float* __restrict__ bf,
                           float* __restrict__ out) {
    int b = blockIdx.x;
    int t = threadIdx.x;            // 512
    __shared__ float xm[DD];
    __shared__ float h1[256];
    __shared__ float h2[128];
    __shared__ float z [LAT];

    float s = 0.f;
#pragma unroll
    for (int i = 0; i < 32; i++) s += g_part[((long)b * 32 + i) * DD + t];
    xm[t] = s * (1.0f / (float)SS);
    __syncthreads();

    if (t < 256) {
        float a = be1[t];
        const float* w = we1 + (long)t * DD;
#pragma unroll 8
        for (int k = 0; k < DD; k++) a += xm[k] * w[k];
        h1[t] = fmaxf(a, 0.f);
    }
    __syncthreads();

    if (t < 128) {
        float a = be2[t];
        const float* w = we2 + (long)t * 256;
#pragma unroll 8
        for (int k = 0; k < 256; k++) a += h1[k] * w[k];
        h2[t] = fmaxf(a, 0.f);
    }
    __syncthreads();

    if (t < LAT) {
        float mu = bmu[t], lv = blv[t];
        const float* w1 = wmu + (long)t * 128;
        const float* w2 = wlv + (long)t * 128;
#pragma unroll 8
        for (int k = 0; k < 128; k++) { mu += h2[k] * w1[k]; lv += h2[k] * w2[k]; }
        out[(long)BB * SS * DD + b * LAT + t]            = mu;
        out[(long)BB * SS * DD + BB * LAT + b * LAT + t] = lv;
        z[t] = mu + eps[b * LAT + t] * expf(0.5f * lv);
    }
    __syncthreads();

    {
        float a = bf[t];
        const float* w = wf + (long)t * LAT;
#pragma unroll
        for (int k = 0; k < LAT; k++) a += z[k] * w[k];
        g_lat[b * DD + t] = a;
    }
}

// ---------------- 3) tf32 GEMM: cp.async 3-stage + ldmatrix ------------------
// Modes: 0=Q (+lat, *1/8, tf32, bhsd)  1=K (+lat, tf32, bhsd)
//        2=V (tf32, transposed (b,h,hd,s))  3=OUT (fp32, (row,col))
#define G_CK      16
#define G_RS      20
#define G_STGF    (2 * 128 * G_RS)
#define G_STAGES  3
#define GEMM_SMEM_BYTES (G_STAGES * G_STGF * 4)   // 61440

template <int MODE>
__global__ __launch_bounds__(256, 2) void gemm_tc(const float* __restrict__ A,
                                                  const float* __restrict__ W,
                                                  const float* __restrict__ bias,
                                                  float* __restrict__ out) {
    extern __shared__ float sm[];
    uint32_t smb = (uint32_t)__cvta_generic_to_shared(sm);

    int tid  = threadIdx.x;
    int lane = tid & 31;
    int wid  = tid >> 5;
    int gID  = lane >> 2;
    int tig  = lane & 3;
    int wm   = wid & 3;
    int wn   = wid >> 2;
    int m0   = blockIdx.x * 128;
    int n0   = blockIdx.y * 128;

    int mtx = lane >> 3;
    int lr  = lane & 7;

    int pr0 = tid >> 2, pc0 = (tid & 3) * 4;
    int pr1 = (tid + 256) >> 2, pc1 = ((tid + 256) & 3) * 4;

    auto prefetch = [&](int c, int st) {
        const float* Asrc = A + (long)(m0 + pr0) * DD + c * G_CK + pc0;
        const float* Wsrc = W + (long)(n0 + pr0) * DD + c * G_CK + pc0;
        CP_A16(smb + (st * G_STGF + pr0 * G_RS + pc0) * 4, Asrc);
        CP_A16(smb + (st * G_STGF + 128 * G_RS + pr0 * G_RS + pc0) * 4, Wsrc);
        const float* Asrc1 = A + (long)(m0 + pr1) * DD + c * G_CK + pc1;
        const float* Wsrc1 = W + (long)(n0 + pr1) * DD + c * G_CK + pc1;
        CP_A16(smb + (st * G_STGF + pr1 * G_RS + pc1) * 4, Asrc1);
        CP_A16(smb + (st * G_STGF + 128 * G_RS + pr1 * G_RS + pc1) * 4, Wsrc1);
    };

    prefetch(0, 0); CP_COMMIT();
    prefetch(1, 1); CP_COMMIT();

    float acc[2][8][4] = {};

    int rowA0 = wm * 32 + (mtx & 1) * 8 + lr;
    int colA  = (mtx >> 1) * 4;
    int rowB0 = wn * 64 + (mtx >> 1) * 8 + lr;
    int colB  = (mtx & 1) * 4;

    const int NCH = DD / G_CK;
    for (int c = 0; c < NCH; c++) {
        CP_WAIT(1);
        __syncthreads();
        if (c + 2 < NCH) prefetch(c + 2, (c + 2) % G_STAGES);
        CP_COMMIT();

        uint32_t stA = smb + ((c % G_STAGES) * G_STGF) * 4;
        uint32_t stW = stA + 128 * G_RS * 4;

#pragma unroll
        for (int ks = 0; ks < 2; ks++) {
            uint32_t a[2][4];
#pragma unroll
            for (int mt = 0; mt < 2; mt++) {
                ldsm4(stA + ((rowA0 + mt * 16) * G_RS + 8 * ks + colA) * 4,
                      a[mt][0], a[mt][1], a[mt][2], a[mt][3]);
            }
            uint32_t b[8][2];
#pragma unroll
            for (int nbp = 0; nbp < 4; nbp++) {
                ldsm4(stW + ((rowB0 + nbp * 16) * G_RS + 8 * ks + colB) * 4,
                      b[2 * nbp][0], b[2 * nbp][1], b[2 * nbp + 1][0], b[2 * nbp + 1][1]);
            }
#pragma unroll
            for (int mt = 0; mt < 2; mt++)
#pragma unroll
                for (int j = 0; j < 4; j++) a[mt][j] = cvt_raw(a[mt][j]);
#pragma unroll
            for (int nb = 0; nb < 8; nb++) {
                b[nb][0] = cvt_raw(b[nb][0]);
                b[nb][1] = cvt_raw(b[nb][1]);
            }
#pragma unroll
            for (int mt = 0; mt < 2; mt++)
#pragma unroll
                for (int nb = 0; nb < 8; nb++)
                    mma_tf32(acc[mt][nb], a[mt][0], a[mt][1], a[mt][2], a[mt][3],
                             b[nb][0], b[nb][1]);
        }
    }

    // epilogue
#pragma unroll
    for (int mt = 0; mt < 2; mt++) {
#pragma unroll
        for (int nb = 0; nb < 8; nb++) {
            int col = n0 + wn * 64 + nb * 8 + 2 * tig;
            float bz0 = bias[col], bz1 = bias[col + 1];
#pragma unroll
            for (int rr = 0; rr < 2; rr++) {
                int row = m0 + wm * 32 + mt * 16 + gID + 8 * rr;
                int b = row >> 12;
                int sidx = row & 4095;
                float v0 = acc[mt][nb][2 * rr + 0] + bz0;
                float v1 = acc[mt][nb][2 * rr + 1] + bz1;
                if (MODE == 0 || MODE == 1) {
                    v0 += g_lat[b * DD + col];
                    v1 += g_lat[b * DD + col + 1];
                    if (MODE == 0) { v0 *= 0.125f; v1 *= 0.125f; }
                    int h  = col >> 6;
                    int hd = col & 63;
                    float2 o = make_float2(u2f(f2tf(v0)), u2f(f2tf(v1)));
                    *(float2*)&out[(((long)(b * HH + h) * SS + sidx) * HDD) + hd] = o;
                } else if (MODE == 2) {
                    int h  = col >> 6;
                    int hd = col & 63;
                    long base = ((long)(b * HH + h) * HDD + hd) * SS + sidx;
                    out[base]      = u2f(f2tf(v0));
                    out[base + SS] = u2f(f2tf(v1));
                } else {
                    *(float2*)&out[(long)row * DD + col] = make_float2(v0, v1);
                }
            }
        }
    }
}

// ---------------- 4) tf32 flash attention: all operands pre-converted -------
// 128 q x 64 k tiles. 8 warps, warp = 16-row strip.
// K smem [key][68], Vt smem [dv][68]; both ldmatrix, conflict-free.
#define F_KST (64 * 68)
#define F_VST (64 * 68)
#define FLASH_SMEM_BYTES ((2 * F_KST + 2 * F_VST) * 4)   // 69632

__global__ __launch_bounds__(256, 2) void flash_tc() {
    extern __shared__ float sm[];
    uint32_t smb = (uint32_t)__cvta_generic_to_shared(sm);

    int tid  = threadIdx.x;
    int lane = tid & 31;
    int wid  = tid >> 5;
    int gID  = lane >> 2;
    int tig  = lane & 3;
    int bh   = blockIdx.y;
    int m0   = blockIdx.x * 128;
    int m0w  = wid * 16;

    int mtx = lane >> 3;
    int lr  = lane & 7;

    const float* Qg = g_q + ((long)bh * SS + m0) * HDD;
    const float* Kg = g_k + (long)bh * SS * HDD;
    const float* Vg = g_v + (long)bh * HDD * SS;   // transposed (hd, s)

    // ---- Q fragments: already tf32 bits, prescaled ----
    uint32_t qa[8][4];
#pragma unroll
    for (int ks = 0; ks < 8; ks++) {
        qa[ks][0] = __float_as_uint(Qg[(m0w + gID)     * HDD + 8 * ks + tig]);
        qa[ks][1] = __float_as_uint(Qg[(m0w + gID + 8) * HDD + 8 * ks + tig]);
        qa[ks][2] = __float_as_uint(Qg[(m0w + gID)     * HDD + 8 * ks + tig + 4]);
        qa[ks][3] = __float_as_uint(Qg[(m0w + gID + 8) * HDD + 8 * ks + tig + 4]);
    }

    // producer: K tile rows = keys, V tile rows = dv (transposed source)
    auto prefetch = [&](int c, int st) {
        long kbase = (long)c * 64 * HDD;
#pragma unroll
        for (int i = 0; i < 4; i++) {
            int s = tid + i * 256;
            int r = s >> 4, sc = (s & 15) * 4;
            CP_A16(smb + (st * F_KST + r * 68 + sc) * 4, Kg + kbase + r * HDD + sc);
            CP_A16(smb + (2 * F_KST + st * F_VST + r * 68 + sc) * 4,
                   Vg + (long)r * SS + c * 64 + sc);
        }
    };

    prefetch(0, 0); CP_COMMIT();

    float oacc[8][4] = {};
    float m0r = -1e30f, m1r = -1e30f;
    float l0 = 0.f, l1 = 0.f;

    int rowB0 = (mtx >> 1) * 8 + lr;      // + nbp*16 (shared by K and Vt)
    int colB  = (mtx & 1) * 4;

    const int NT = SS / 64;
    for (int c = 0; c < NT; c++) {
        CP_WAIT(0);
        __syncthreads();
        if (c + 1 < NT) prefetch(c + 1, (c + 1) & 1);
        CP_COMMIT();

        uint32_t stK = smb + ((c & 1) * F_KST) * 4;
        uint32_t stV = smb + (2 * F_KST + (c & 1) * F_VST) * 4;

        // ---- S = Q @ K^T ----
        float sacc[8][4] = {};
#pragma unroll
        for (int ks = 0; ks < 8; ks++) {
            uint32_t b[8][2];
#pragma unroll
            for (int nbp = 0; nbp < 4; nbp++) {
                ldsm4(stK + ((rowB0 + nbp * 16) * 68 + 8 * ks + colB) * 4,
                      b[2 * nbp][0], b[2 * nbp][1], b[2 * nbp + 1][0], b[2 * nbp + 1][1]);
            }
#pragma unroll
            for (int nb = 0; nb < 8; nb++)
                mma_tf32(sacc[nb], qa[ks][0], qa[ks][1], qa[ks][2], qa[ks][3],
                         b[nb][0], b[nb][1]);
        }

        // ---- online softmax (warp-local quad reduction) ----
        float mx0 = -1e30f, mx1 = -1e30f;
#pragma unroll
        for (int nb = 0; nb < 8; nb++) {
            mx0 = fmaxf(mx0, fmaxf(sacc[nb][0], sacc[nb][1]));
            mx1 = fmaxf(mx1, fmaxf(sacc[nb][2], sacc[nb][3]));
        }
        mx0 = fmaxf(mx0, __shfl_xor_sync(0xffffffffu, mx0, 1));
        mx0 = fmaxf(mx0, __shfl_xor_sync(0xffffffffu, mx0, 2));
        mx1 = fmaxf(mx1, __shfl_xor_sync(0xffffffffu, mx1, 1));
        mx1 = fmaxf(mx1, __shfl_xor_sync(0xffffffffu, mx1, 2));

        float nm0 = fmaxf(m0r, mx0);
        float nm1 = fmaxf(m1r, mx1);
        float c0 = __expf(m0r - nm0);
        float c1 = __expf(m1r - nm1);
        m0r = nm0; m1r = nm1;

        uint32_t pf[8][4];
        float s0 = 0.f, s1 = 0.f;
#pragma unroll
        for (int nb = 0; nb < 8; nb++) {
            pf[nb][0] = f2tf(__expf(sacc[nb][0] - nm0));
            pf[nb][1] = f2tf(__expf(sacc[nb][1] - nm0));
            pf[nb][2] = f2tf(__expf(sacc[nb][2] - nm1));
            pf[nb][3] = f2tf(__expf(sacc[nb][3] - nm1));
            s0 += u2f(pf[nb][0]) + u2f(pf[nb][1]);
            s1 += u2f(pf[nb][2]) + u2f(pf[nb][3]);
        }
        s0 += __shfl_xor_sync(0xffffffffu, s0, 1);
        s0 += __shfl_xor_sync(0xffffffffu, s0, 2);
        s1 += __shfl_xor_sync(0xffffffffu, s1, 1);
        s1 += __shfl_xor_sync(0xffffffffu, s1, 2);
        l0 = l0 * c0 + s0;
        l1 = l1 * c1 + s1;
#pragma unroll
        for (int nb = 0; nb < 8; nb++) {
            oacc[nb][0] *= c0; oacc[nb][1] *= c0;
            oacc[nb][2] *= c1; oacc[nb][3] *= c1;
        }

        // ---- O += P @ V  (P shuffled to A-frag; Vt via ldmatrix) ----
#pragma unroll
        for (int ks = 0; ks < 8; ks++) {
            int base = lane & ~3;
            int s1i = base + (tig >> 1);
            int s2i = s1i + 2;
            uint32_t v00 = __shfl_sync(0xffffffffu, pf[ks][0], s1i);
            uint32_t v01 = __shfl_sync(0xffffffffu, pf[ks][1], s1i);
            uint32_t v10 = __shfl_sync(0xffffffffu, pf[ks][2], s1i);
            uint32_t v11 = __shfl_sync(0xffffffffu, pf[ks][3], s1i);
            uint32_t w00 = __shfl_sync(0xffffffffu, pf[ks][0], s2i);
            uint32_t w01 = __shfl_sync(0xffffffffu, pf[ks][1], s2i);
            uint32_t w10 = __shfl_sync(0xffffffffu, pf[ks][2], s2i);
            uint32_t w11 = __shfl_sync(0xffffffffu, pf[ks][3], s2i);
            uint32_t pa0 = (tig & 1) ? v01 : v00;
            uint32_t pa1 = (tig & 1) ? v11 : v10;
            uint32_t pa2 = (tig & 1) ? w01 : w00;
            uint32_t pa3 = (tig & 1) ? w11 : w10;

            uint32_t vb[8][2];
#pragma unroll
            for (int nbp = 0; nbp < 4; nbp++) {
                ldsm4(stV + ((rowB0 + nbp * 16) * 68 + 8 * ks + colB) * 4,
                      vb[2 * nbp][0], vb[2 * nbp][1], vb[2 * nbp + 1][0], vb[2 * nbp + 1][1]);
            }
#pragma unroll
            for (int nb = 0; nb < 8; nb++)
                mma_tf32(oacc[nb], pa0, pa1, pa2, pa3, vb[nb][0], vb[nb][1]);
        }
    }

    // ---- normalize + write ctx (b,s,d) ----
    int b = bh >> 3, h = bh & 7;
    float inv0 = 1.0f / l0;
    float inv1 = 1.0f / l1;
#pragma unroll
    for (int nb = 0; nb < 8; nb++) {
        int dv = 8 * nb + 2 * tig;
        long row0 = (long)b * SS + m0 + m0w + gID;
        long row1 = row0 + 8;
        *(float2*)&g_ctx[row0 * DD + h * HDD + dv] =
            make_float2(oacc[nb][0] * inv0, oacc[nb][1] * inv0);
        *(float2*)&g_ctx[row1 * DD + h * HDD + dv] =
            make_float2(oacc[nb][2] * inv1, oacc[nb][3] * inv1);
    }
}

// ---------------- launch ----------------
extern "C" void kernel_launch(void* const* d_in, const int* in_sizes, int n_in,
                              void* d_out, int out_size) {
    const float* x   = (const float*)d_in[0];
    const float* eps = (const float*)d_in[1];
    const float* wq  = (const float*)d_in[2];  const float* bq  = (const float*)d_in[3];
    const float* wk  = (const float*)d_in[4];  const float* bk  = (const float*)d_in[5];
    const float* wv  = (const float*)d_in[6];  const float* bv  = (const float*)d_in[7];
    const float* wo  = (const float*)d_in[8];  const float* bo  = (const float*)d_in[9];
    const float* we1 = (const float*)d_in[10]; const float* be1 = (const float*)d_in[11];
    const float* we2 = (const float*)d_in[12]; const float* be2 = (const float*)d_in[13];
    const float* wmu = (const float*)d_in[14]; const float* bmu = (const float*)d_in[15];
    const float* wlv = (const float*)d_in[16]; const float* blv = (const float*)d_in[17];
    const float* wf  = (const float*)d_in[18]; const float* bf  = (const float*)d_in[19];
    float* out = (float*)d_out;

    void *pq, *pk, *pv, *pctx;
    cudaGetSymbolAddress(&pq,  g_q);
    cudaGetSymbolAddress(&pk,  g_k);
    cudaGetSymbolAddress(&pv,  g_v);
    cudaGetSymbolAddress(&pctx, g_ctx);

    cudaFuncSetAttribute(gemm_tc<0>, cudaFuncAttributeMaxDynamicSharedMemorySize, GEMM_SMEM_BYTES);
    cudaFuncSetAttribute(gemm_tc<1>, cudaFuncAttributeMaxDynamicSharedMemorySize, GEMM_SMEM_BYTES);
    cudaFuncSetAttribute(gemm_tc<2>, cudaFuncAttributeMaxDynamicSharedMemorySize, GEMM_SMEM_BYTES);
    cudaFuncSetAttribute(gemm_tc<3>, cudaFuncAttributeMaxDynamicSharedMemorySize, GEMM_SMEM_BYTES);
    cudaFuncSetAttribute(flash_tc, cudaFuncAttributeMaxDynamicSharedMemorySize, FLASH_SMEM_BYTES);

    mean_partial<<<BB * 32, DD>>>(x);
    vae_kernel<<<BB, DD>>>(eps, we1, be1, we2, be2, wmu, bmu, wlv, blv, wf, bf, out);

    dim3 gg((BB * SS) / 128, DD / 128);
    gemm_tc<0><<<gg, 256, GEMM_SMEM_BYTES>>>(x, wq, bq, (float*)pq);
    gemm_tc<1><<<gg, 256, GEMM_SMEM_BYTES>>>(x, wk, bk, (float*)pk);
    gemm_tc<2><<<gg, 256, GEMM_SMEM_BYTES>>>(x, wv, bv, (float*)pv);

    flash_tc<<<dim3(SS / 128, BB * HH), 256, FLASH_SMEM_BYTES>>>();

    gemm_tc<3><<<gg, 256, GEMM_SMEM_BYTES>>>((float*)pctx, wo, bo, out);
}

// round 8
// speedup vs baseline: 4.5854x; 1.4629x over previous
#include <cuda_runtime.h>
#include <cuda_fp16.h>
#include <math.h>
#include <stdint.h>

#define BB   2
#define SS   4096
#define DD   512
#define HH   8
#define HDD  64
#define LAT  64

// ---------------- scratch (static device globals; no allocs) ----------------
__device__ float  g_part[BB * 32 * DD];
__device__ float  g_lat [BB * DD];
__device__ __half g_q   [BB * HH * SS * HDD];   // (b,h,s,hd)  f16, prescaled 1/8
__device__ __half g_k   [BB * HH * SS * HDD];   // (b,h,s,hd)  f16
__device__ __half g_v   [BB * HH * HDD * SS];   // (b,h,hd,s)  f16 (TRANSPOSED)
__device__ float  g_ctx [BB * SS * DD];         // (b,s,d)  fp32

// ---------------- helpers ----------------
__device__ __forceinline__ uint32_t f2tf(float f) {
    uint32_t r;
    asm("cvt.rna.tf32.f32 %0, %1;" : "=r"(r) : "f"(f));
    return r;
}
__device__ __forceinline__ uint32_t cvt_raw(uint32_t raw) {
    return f2tf(__uint_as_float(raw));
}
__device__ __forceinline__ float u2f(uint32_t u) { return __uint_as_float(u); }

// pack {lo, hi} floats -> f16x2 reg  (PTX: first src -> upper half)
__device__ __forceinline__ uint32_t packh2(float lo, float hi) {
    uint32_t d;
    asm("cvt.rn.f16x2.f32 %0, %1, %2;" : "=r"(d) : "f"(hi), "f"(lo));
    return d;
}

__device__ __forceinline__ void mma_tf32(float* c, uint32_t a0, uint32_t a1,
                                         uint32_t a2, uint32_t a3,
                                         uint32_t b0, uint32_t b1) {
    asm volatile(
        "mma.sync.aligned.m16n8k8.row.col.f32.tf32.tf32.f32 "
        "{%0,%1,%2,%3}, {%4,%5,%6,%7}, {%8,%9}, {%0,%1,%2,%3};\n"
        : "+f"(c[0]), "+f"(c[1]), "+f"(c[2]), "+f"(c[3])
        : "r"(a0), "r"(a1), "r"(a2), "r"(a3), "r"(b0), "r"(b1));
}

__device__ __forceinline__ void mma_f16(float* c, uint32_t a0, uint32_t a1,
                                        uint32_t a2, uint32_t a3,
                                        uint32_t b0, uint32_t b1) {
    asm volatile(
        "mma.sync.aligned.m16n8k16.row.col.f32.f16.f16.f32 "
        "{%0,%1,%2,%3}, {%4,%5,%6,%7}, {%8,%9}, {%0,%1,%2,%3};\n"
        : "+f"(c[0]), "+f"(c[1]), "+f"(c[2]), "+f"(c[3])
        : "r"(a0), "r"(a1), "r"(a2), "r"(a3), "r"(b0), "r"(b1));
}

__device__ __forceinline__ void ldsm4(uint32_t addr, uint32_t& r0, uint32_t& r1,
                                      uint32_t& r2, uint32_t& r3) {
    asm volatile("ldmatrix.sync.aligned.m8n8.x4.shared.b16 {%0,%1,%2,%3}, [%4];\n"
                 : "=r"(r0), "=r"(r1), "=r"(r2), "=r"(r3) : "r"(addr));
}

#define CP_A16(dst, src) \
    asm volatile("cp.async.ca.shared.global [%0], [%1], 16;\n" :: "r"(dst), "l"(src))
#define CP_COMMIT() asm volatile("cp.async.commit_group;\n" ::: "memory")
#define CP_WAIT(n)  asm volatile("cp.async.wait_group %0;\n" :: "n"(n) : "memory")

// ---------------- 1) mean over sequence: partial sums ----------------
__global__ void mean_partial(const float* __restrict__ x) {
    int bx = blockIdx.x;
    int b  = bx >> 5;
    int sp = bx & 31;
    int t  = threadIdx.x;           // 512
    const int chunk = SS / 32;
    const float* p = x + ((long)b * SS + (long)sp * chunk) * DD + t;
    float s = 0.f;
#pragma unroll 4
    for (int i = 0; i < chunk; i++) s += p[(long)i * DD];
    g_part[(long)bx * DD + t] = s;
}

// ---------------- 2) VAE MLP ----------------
__global__ void vae_kernel(const float* __restrict__ eps,
                           const float* __restrict__ we1, const float* __restrict__ be1,
                           const float* __restrict__ we2, const float* __restrict__ be2,
                           const float* __restrict__ wmu, const float* __restrict__ bmu,
                           const float* __restrict__ wlv, const float* __restrict__ blv,
                           const float* __restrict__ wf,  const float* __restrict__ bf,
                           float* __restrict__ out) {
    int b = blockIdx.x;
    int t = threadIdx.x;            // 512
    __shared__ float xm[DD];
    __shared__ float h1[256];
    __shared__ float h2[128];
    __shared__ float z [LAT];

    float s = 0.f;
#pragma unroll
    for (int i = 0; i < 32; i++) s += g_part[((long)b * 32 + i) * DD + t];
    xm[t] = s * (1.0f / (float)SS);
    __syncthreads();

    if (t < 256) {
        float a = be1[t];
        const float* w = we1 + (long)t * DD;
#pragma unroll 8
        for (int k = 0; k < DD; k++) a += xm[k] * w[k];
        h1[t] = fmaxf(a, 0.f);
    }
    __syncthreads();

    if (t < 128) {
        float a = be2[t];
        const float* w = we2 + (long)t * 256;
#pragma unroll 8
        for (int k = 0; k < 256; k++) a += h1[k] * w[k];
        h2[t] = fmaxf(a, 0.f);
    }
    __syncthreads();

    if (t < LAT) {
        float mu = bmu[t], lv = blv[t];
        const float* w1 = wmu + (long)t * 128;
        const float* w2 = wlv + (long)t * 128;
#pragma unroll 8
        for (int k = 0; k < 128; k++) { mu += h2[k] * w1[k]; lv += h2[k] * w2[k]; }
        out[(long)BB * SS * DD + b * LAT + t]            = mu;
        out[(long)BB * SS * DD + BB * LAT + b * LAT + t] = lv;
        z[t] = mu + eps[b * LAT + t] * expf(0.5f * lv);
    }
    __syncthreads();

    {
        float a = bf[t];
        const float* w = wf + (long)t * LAT;
#pragma unroll
        for (int k = 0; k < LAT; k++) a += z[k] * w[k];
        g_lat[b * DD + t] = a;
    }
}

// ---------------- 3) tf32 GEMM: cp.async 3-stage + ldmatrix ------------------
// Modes: 0=Q (+lat, *1/8, f16, bhsd)  1=K (+lat, f16, bhsd)
//        2=V (f16, transposed (b,h,hd,s))  3=OUT (fp32, (row,col))
#define G_CK      16
#define G_RS      20
#define G_STGF    (2 * 128 * G_RS)
#define G_STAGES  3
#define GEMM_SMEM_BYTES (G_STAGES * G_STGF * 4)   // 61440

template <int MODE>
__global__ __launch_bounds__(256, 2) void gemm_tc(const float* __restrict__ A,
                                                  const float* __restrict__ W,
                                                  const float* __restrict__ bias,
                                                  void* __restrict__ out_) {
    extern __shared__ float sm[];
    uint32_t smb = (uint32_t)__cvta_generic_to_shared(sm);

    int tid  = threadIdx.x;
    int lane = tid & 31;
    int wid  = tid >> 5;
    int gID  = lane >> 2;
    int tig  = lane & 3;
    int wm   = wid & 3;
    int wn   = wid >> 2;
    int m0   = blockIdx.x * 128;
    int n0   = blockIdx.y * 128;

    int mtx = lane >> 3;
    int lr  = lane & 7;

    int pr0 = tid >> 2, pc0 = (tid & 3) * 4;
    int pr1 = (tid + 256) >> 2, pc1 = ((tid + 256) & 3) * 4;

    auto prefetch = [&](int c, int st) {
        const float* Asrc = A + (long)(m0 + pr0) * DD + c * G_CK + pc0;
        const float* Wsrc = W + (long)(n0 + pr0) * DD + c * G_CK + pc0;
        CP_A16(smb + (st * G_STGF + pr0 * G_RS + pc0) * 4, Asrc);
        CP_A16(smb + (st * G_STGF + 128 * G_RS + pr0 * G_RS + pc0) * 4, Wsrc);
        const float* Asrc1 = A + (long)(m0 + pr1) * DD + c * G_CK + pc1;
        const float* Wsrc1 = W + (long)(n0 + pr1) * DD + c * G_CK + pc1;
        CP_A16(smb + (st * G_STGF + pr1 * G_RS + pc1) * 4, Asrc1);
        CP_A16(smb + (st * G_STGF + 128 * G_RS + pr1 * G_RS + pc1) * 4, Wsrc1);
    };

    prefetch(0, 0); CP_COMMIT();
    prefetch(1, 1); CP_COMMIT();

    float acc[2][8][4] = {};

    int rowA0 = wm * 32 + (mtx & 1) * 8 + lr;
    int colA  = (mtx >> 1) * 4;
    int rowB0 = wn * 64 + (mtx >> 1) * 8 + lr;
    int colB  = (mtx & 1) * 4;

    const int NCH = DD / G_CK;
    for (int c = 0; c < NCH; c++) {
        CP_WAIT(1);
        __syncthreads();
        if (c + 2 < NCH) prefetch(c + 2, (c + 2) % G_STAGES);
        CP_COMMIT();

        uint32_t stA = smb + ((c % G_STAGES) * G_STGF) * 4;
        uint32_t stW = stA + 128 * G_RS * 4;

#pragma unroll
        for (int ks = 0; ks < 2; ks++) {
            uint32_t a[2][4];
#pragma unroll
            for (int mt = 0; mt < 2; mt++) {
                ldsm4(stA + ((rowA0 + mt * 16) * G_RS + 8 * ks + colA) * 4,
                      a[mt][0], a[mt][1], a[mt][2], a[mt][3]);
            }
            uint32_t b[8][2];
#pragma unroll
            for (int nbp = 0; nbp < 4; nbp++) {
                ldsm4(stW + ((rowB0 + nbp * 16) * G_RS + 8 * ks + colB) * 4,
                      b[2 * nbp][0], b[2 * nbp][1], b[2 * nbp + 1][0], b[2 * nbp + 1][1]);
            }
#pragma unroll
            for (int mt = 0; mt < 2; mt++)
#pragma unroll
                for (int j = 0; j < 4; j++) a[mt][j] = cvt_raw(a[mt][j]);
#pragma unroll
            for (int nb = 0; nb < 8; nb++) {
                b[nb][0] = cvt_raw(b[nb][0]);
                b[nb][1] = cvt_raw(b[nb][1]);
            }
#pragma unroll
            for (int mt = 0; mt < 2; mt++)
#pragma unroll
                for (int nb = 0; nb < 8; nb++)
                    mma_tf32(acc[mt][nb], a[mt][0], a[mt][1], a[mt][2], a[mt][3],
                             b[nb][0], b[nb][1]);
        }
    }

    // epilogue
    float*  outf = (float*)out_;
    __half* outh = (__half*)out_;
#pragma unroll
    for (int mt = 0; mt < 2; mt++) {
#pragma unroll
        for (int nb = 0; nb < 8; nb++) {
            int col = n0 + wn * 64 + nb * 8 + 2 * tig;
            float bz0 = bias[col], bz1 = bias[col + 1];
#pragma unroll
            for (int rr = 0; rr < 2; rr++) {
                int row = m0 + wm * 32 + mt * 16 + gID + 8 * rr;
                int b = row >> 12;
                int sidx = row & 4095;
                float v0 = acc[mt][nb][2 * rr + 0] + bz0;
                float v1 = acc[mt][nb][2 * rr + 1] + bz1;
                if (MODE == 0 || MODE == 1) {
                    v0 += g_lat[b * DD + col];
                    v1 += g_lat[b * DD + col + 1];
                    if (MODE == 0) { v0 *= 0.125f; v1 *= 0.125f; }
                    int h  = col >> 6;
                    int hd = col & 63;
                    __half2 o = __floats2half2_rn(v0, v1);
                    *(__half2*)&outh[(((long)(b * HH + h) * SS + sidx) * HDD) + hd] = o;
                } else if (MODE == 2) {
                    int h  = col >> 6;
                    int hd = col & 63;
                    long base = ((long)(b * HH + h) * HDD + hd) * SS + sidx;
                    outh[base]      = __float2half_rn(v0);
                    outh[base + SS] = __float2half_rn(v1);
                } else {
                    *(float2*)&outf[(long)row * DD + col] = make_float2(v0, v1);
                }
            }
        }
    }
}

// ---------------- 4) f16 flash attention ------------------------------------
// 128 q x 64 k tiles. 8 warps, warp = 16-row strip. m16n8k16 f16, fp32 accum.
// K tile: half [64 keys][72], Vt tile: half [64 dv][72]. ldmatrix non-trans.
#define F_TB  (64 * 72 * 2)                 // 9216 bytes per tile
#define FLASH_SMEM_BYTES (4 * F_TB)         // 36864  [K0,K1,V0,V1]

__global__ __launch_bounds__(256, 2) void flash_tc() {
    extern __shared__ char smc[];
    uint32_t smb = (uint32_t)__cvta_generic_to_shared(smc);

    int tid  = threadIdx.x;
    int lane = tid & 31;
    int wid  = tid >> 5;
    int gID  = lane >> 2;
    int tig  = lane & 3;
    int bh   = blockIdx.y;
    int m0   = blockIdx.x * 128;
    int m0w  = wid * 16;

    int grp = lane >> 3;
    int lr  = lane & 7;

    const __half* Qg = g_q + ((long)bh * SS + m0) * HDD;
    const __half* Kg = g_k + (long)bh * SS * HDD;
    const __half* Vg = g_v + (long)bh * HDD * SS;   // (hd, s)

    // ---- Q A-fragments from global (f16 pairs; prescaled 1/8) ----
    const uint32_t* Qg32 = (const uint32_t*)Qg;
    uint32_t qa[4][4];
#pragma unroll
    for (int ks = 0; ks < 4; ks++) {
        qa[ks][0] = Qg32[(m0w + gID)     * 32 + 8 * ks + tig];
        qa[ks][1] = Qg32[(m0w + gID + 8) * 32 + 8 * ks + tig];
        qa[ks][2] = Qg32[(m0w + gID)     * 32 + 8 * ks + tig + 4];
        qa[ks][3] = Qg32[(m0w + gID + 8) * 32 + 8 * ks + tig + 4];
    }

    // producer: 512 16B-segs each for K,V per tile; 2 iterations/thread
    auto prefetch = [&](int c, int st) {
#pragma unroll
        for (int i = 0; i < 2; i++) {
            int s = tid + i * 256;
            int r = s >> 3, ch = (s & 7) * 8;             // halfs
            CP_A16(smb + st * F_TB + (r * 72 + ch) * 2,
                   Kg + (long)(c * 64 + r) * HDD + ch);
            CP_A16(smb + 2 * F_TB + st * F_TB + (r * 72 + ch) * 2,
                   Vg + (long)r * SS + c * 64 + ch);
        }
    };

    prefetch(0, 0); CP_COMMIT();

    float oacc[8][4] = {};
    float m0r = -1e30f, m1r = -1e30f;
    float l0 = 0.f, l1 = 0.f;

    // per-lane ldmatrix offsets: row = nbp*16 + (grp>>1)*8 + lr; col = 16ks + (grp&1)*8
    uint32_t lmBase = (((grp >> 1) * 8 + lr) * 72 + (grp & 1) * 8) * 2;

    const int NT = SS / 64;
    for (int c = 0; c < NT; c++) {
        CP_WAIT(0);
        __syncthreads();
        if (c + 1 < NT) prefetch(c + 1, (c + 1) & 1);
        CP_COMMIT();

        uint32_t stK = smb + (c & 1) * F_TB;
        uint32_t stV = smb + 2 * F_TB + (c & 1) * F_TB;

        // ---- S = Q @ K^T  (m16n8k16) ----
        float sacc[8][4] = {};
#pragma unroll
        for (int ks = 0; ks < 4; ks++) {
#pragma unroll
            for (int nbp = 0; nbp < 4; nbp++) {
                uint32_t b0, b1, b2, b3;
                ldsm4(stK + lmBase + nbp * (16 * 144) + ks * 32, b0, b1, b2, b3);
                mma_f16(sacc[2 * nbp],     qa[ks][0], qa[ks][1], qa[ks][2], qa[ks][3], b0, b1);
                mma_f16(sacc[2 * nbp + 1], qa[ks][0], qa[ks][1], qa[ks][2], qa[ks][3], b2, b3);
            }
        }

        // ---- online softmax (warp-local quad reduction) ----
        float mx0 = -1e30f, mx1 = -1e30f;
#pragma unroll
        for (int nb = 0; nb < 8; nb++) {
            mx0 = fmaxf(mx0, fmaxf(sacc[nb][0], sacc[nb][1]));
            mx1 = fmaxf(mx1, fmaxf(sacc[nb][2], sacc[nb][3]));
        }
        mx0 = fmaxf(mx0, __shfl_xor_sync(0xffffffffu, mx0, 1));
        mx0 = fmaxf(mx0, __shfl_xor_sync(0xffffffffu, mx0, 2));
        mx1 = fmaxf(mx1, __shfl_xor_sync(0xffffffffu, mx1, 1));
        mx1 = fmaxf(mx1, __shfl_xor_sync(0xffffffffu, mx1, 2));

        float nm0 = fmaxf(m0r, mx0);
        float nm1 = fmaxf(m1r, mx1);
        float c0 = __expf(m0r - nm0);
        float c1 = __expf(m1r - nm1);
        m0r = nm0; m1r = nm1;

        // P = exp(S - m), packed straight into f16 A-fragments (no shuffles)
        uint32_t pa[4][4];
        float s0 = 0.f, s1 = 0.f;
#pragma unroll
        for (int ks = 0; ks < 4; ks++) {
            float p00 = __expf(sacc[2 * ks][0] - nm0);
            float p01 = __expf(sacc[2 * ks][1] - nm0);
            float p02 = __expf(sacc[2 * ks][2] - nm1);
            float p03 = __expf(sacc[2 * ks][3] - nm1);
            float p10 = __expf(sacc[2 * ks + 1][0] - nm0);
            float p11 = __expf(sacc[2 * ks + 1][1] - nm0);
            float p12 = __expf(sacc[2 * ks + 1][2] - nm1);
            float p13 = __expf(sacc[2 * ks + 1][3] - nm1);
            pa[ks][0] = packh2(p00, p01);
            pa[ks][1] = packh2(p02, p03);
            pa[ks][2] = packh2(p10, p11);
            pa[ks][3] = packh2(p12, p13);
            s0 += p00 + p01 + p10 + p11;
            s1 += p02 + p03 + p12 + p13;
        }
        s0 += __shfl_xor_sync(0xffffffffu, s0, 1);
        s0 += __shfl_xor_sync(0xffffffffu, s0, 2);
        s1 += __shfl_xor_sync(0xffffffffu, s1, 1);
        s1 += __shfl_xor_sync(0xffffffffu, s1, 2);
        l0 = l0 * c0 + s0;
        l1 = l1 * c1 + s1;
#pragma unroll
        for (int nb = 0; nb < 8; nb++) {
            oacc[nb][0] *= c0; oacc[nb][1] *= c0;
            oacc[nb][2] *= c1; oacc[nb][3] *= c1;
        }

        // ---- O += P @ V  (Vt B-frags via ldmatrix; rows = dv) ----
#pragma unroll
        for (int ks = 0; ks < 4; ks++) {
#pragma unroll
            for (int nbp = 0; nbp < 4; nbp++) {
                uint32_t v0, v1, v2, v3;
                ldsm4(stV + lmBase + nbp * (16 * 144) + ks * 32, v0, v1, v2, v3);
                mma_f16(oacc[2 * nbp],     pa[ks][0], pa[ks][1], pa[ks][2], pa[ks][3], v0, v1);
                mma_f16(oacc[2 * nbp + 1], pa[ks][0], pa[ks][1], pa[ks][2], pa[ks][3], v2, v3);
            }
        }
    }

    // ---- normalize + write ctx (b,s,d) ----
    int b = bh >> 3, h = bh & 7;
    float inv0 = 1.0f / l0;
    float inv1 = 1.0f / l1;
#pragma unroll
    for (int nb = 0; nb < 8; nb++) {
        int dv = 8 * nb + 2 * tig;
        long row0 = (long)b * SS + m0 + m0w + gID;
        long row1 = row0 + 8;
        *(float2*)&g_ctx[row0 * DD + h * HDD + dv] =
            make_float2(oacc[nb][0] * inv0, oacc[nb][1] * inv0);
        *(float2*)&g_ctx[row1 * DD + h * HDD + dv] =
            make_float2(oacc[nb][2] * inv1, oacc[nb][3] * inv1);
    }
}

// ---------------- launch ----------------
extern "C" void kernel_launch(void* const* d_in, const int* in_sizes, int n_in,
                              void* d_out, int out_size) {
    const float* x   = (const float*)d_in[0];
    const float* eps = (const float*)d_in[1];
    const float* wq  = (const float*)d_in[2];  const float* bq  = (const float*)d_in[3];
    const float* wk  = (const float*)d_in[4];  const float* bk  = (const float*)d_in[5];
    const float* wv  = (const float*)d_in[6];  const float* bv  = (const float*)d_in[7];
    const float* wo  = (const float*)d_in[8];  const float* bo  = (const float*)d_in[9];
    const float* we1 = (const float*)d_in[10]; const float* be1 = (const float*)d_in[11];
    const float* we2 = (const float*)d_in[12]; const float* be2 = (const float*)d_in[13];
    const float* wmu = (const float*)d_in[14]; const float* bmu = (const float*)d_in[15];
    const float* wlv = (const float*)d_in[16]; const float* blv = (const float*)d_in[17];
    const float* wf  = (const float*)d_in[18]; const float* bf  = (const float*)d_in[19];
    float* out = (float*)d_out;

    void *pq, *pk, *pv, *pctx;
    cudaGetSymbolAddress(&pq,  g_q);
    cudaGetSymbolAddress(&pk,  g_k);
    cudaGetSymbolAddress(&pv,  g_v);
    cudaGetSymbolAddress(&pctx, g_ctx);

    cudaFuncSetAttribute(gemm_tc<0>, cudaFuncAttributeMaxDynamicSharedMemorySize, GEMM_SMEM_BYTES);
    cudaFuncSetAttribute(gemm_tc<1>, cudaFuncAttributeMaxDynamicSharedMemorySize, GEMM_SMEM_BYTES);
    cudaFuncSetAttribute(gemm_tc<2>, cudaFuncAttributeMaxDynamicSharedMemorySize, GEMM_SMEM_BYTES);
    cudaFuncSetAttribute(gemm_tc<3>, cudaFuncAttributeMaxDynamicSharedMemorySize, GEMM_SMEM_BYTES);
    cudaFuncSetAttribute(flash_tc, cudaFuncAttributeMaxDynamicSharedMemorySize, FLASH_SMEM_BYTES);

    mean_partial<<<BB * 32, DD>>>(x);
    vae_kernel<<<BB, DD>>>(eps, we1, be1, we2, be2, wmu, bmu, wlv, blv, wf, bf, out);

    dim3 gg((BB * SS) / 128, DD / 128);
    gemm_tc<0><<<gg, 256, GEMM_SMEM_BYTES>>>(x, wq, bq, pq);
    gemm_tc<1><<<gg, 256, GEMM_SMEM_BYTES>>>(x, wk, bk, pk);
    gemm_tc<2><<<gg, 256, GEMM_SMEM_BYTES>>>(x, wv, bv, pv);

    flash_tc<<<dim3(SS / 128, BB * HH), 256, FLASH_SMEM_BYTES>>>();

    gemm_tc<3><<<gg, 256, GEMM_SMEM_BYTES>>>((float*)pctx, wo, bo, out);
}

// round 9
// speedup vs baseline: 5.5220x; 1.2042x over previous
#include <cuda_runtime.h>
#include <cuda_fp16.h>
#include <math.h>
#include <stdint.h>

#define BB   2
#define SS   4096
#define DD   512
#define HH   8
#define HDD  64
#define LAT  64

// ---------------- scratch (static device globals; no allocs) ----------------
__device__ float  g_part[BB * 32 * DD];
__device__ float  g_lat [BB * DD];
__device__ __half g_xh  [BB * SS * DD];         // x in f16
__device__ __half g_wh  [4 * DD * DD];          // wq,wk,wv,wo in f16
__device__ __half g_q   [BB * HH * SS * HDD];   // (b,h,s,hd)  f16, prescaled 1/8
__device__ __half g_k   [BB * HH * SS * HDD];   // (b,h,s,hd)  f16
__device__ __half g_v   [BB * HH * HDD * SS];   // (b,h,hd,s)  f16 (TRANSPOSED)
__device__ __half g_ctx [BB * SS * DD];         // (b,s,d)  f16

// ---------------- helpers ----------------
__device__ __forceinline__ float u2f(uint32_t u) { return __uint_as_float(u); }

__device__ __forceinline__ uint32_t packh2(float lo, float hi) {
    uint32_t d;
    asm("cvt.rn.f16x2.f32 %0, %1, %2;" : "=r"(d) : "f"(hi), "f"(lo));
    return d;
}

__device__ __forceinline__ void mma_f16(float* c, uint32_t a0, uint32_t a1,
                                        uint32_t a2, uint32_t a3,
                                        uint32_t b0, uint32_t b1) {
    asm volatile(
        "mma.sync.aligned.m16n8k16.row.col.f32.f16.f16.f32 "
        "{%0,%1,%2,%3}, {%4,%5,%6,%7}, {%8,%9}, {%0,%1,%2,%3};\n"
        : "+f"(c[0]), "+f"(c[1]), "+f"(c[2]), "+f"(c[3])
        : "r"(a0), "r"(a1), "r"(a2), "r"(a3), "r"(b0), "r"(b1));
}

__device__ __forceinline__ void ldsm4(uint32_t addr, uint32_t& r0, uint32_t& r1,
                                      uint32_t& r2, uint32_t& r3) {
    asm volatile("ldmatrix.sync.aligned.m8n8.x4.shared.b16 {%0,%1,%2,%3}, [%4];\n"
                 : "=r"(r0), "=r"(r1), "=r"(r2), "=r"(r3) : "r"(addr));
}

#define CP_A16(dst, src) \
    asm volatile("cp.async.ca.shared.global [%0], [%1], 16;\n" :: "r"(dst), "l"(src))
#define CP_COMMIT() asm volatile("cp.async.commit_group;\n" ::: "memory")
#define CP_WAIT(n)  asm volatile("cp.async.wait_group %0;\n" :: "n"(n) : "memory")

// ---------------- 0) weight conversion (one-shot, tiny) ----------------
__global__ void conv_weights(const float* __restrict__ wq, const float* __restrict__ wk,
                             const float* __restrict__ wv, const float* __restrict__ wo) {
    int i = blockIdx.x * blockDim.x + threadIdx.x;     // 0 .. 262143
    const float* src[4] = {wq, wk, wv, wo};
#pragma unroll
    for (int m = 0; m < 4; m++) {
        float v = src[m][i];
        g_wh[m * DD * DD + i] = __float2half_rn(v);
    }
}

// ---------------- 1) mean partials + x -> f16 ----------------
__global__ void mean_partial(const float* __restrict__ x) {
    int bx = blockIdx.x;
    int b  = bx >> 5;
    int sp = bx & 31;
    int t  = threadIdx.x;           // 512
    const int chunk = SS / 32;      // 128
    long base = ((long)b * SS + (long)sp * chunk) * DD + t;
    const float* p = x + base;
    float s = 0.f;
#pragma unroll 4
    for (int i = 0; i < chunk; i++) {
        float v = p[(long)i * DD];
        s += v;
        g_xh[base + (long)i * DD] = __float2half_rn(v);
    }
    g_part[(long)bx * DD + t] = s;
}

// ---------------- 2) VAE MLP ----------------
__global__ void vae_kernel(const float* __restrict__ eps,
                           const float* __restrict__ we1, const float* __restrict__ be1,
                           const float* __restrict__ we2, const float* __restrict__ be2,
                           const float* __restrict__ wmu, const float* __restrict__ bmu,
                           const float* __restrict__ wlv, const float* __restrict__ blv,
                           const float* __restrict__ wf,  const float* __restrict__ bf,
                           float* __restrict__ out) {
    int b = blockIdx.x;
    int t = threadIdx.x;            // 512
    __shared__ float xm[DD];
    __shared__ float h1[256];
    __shared__ float h2[128];
    __shared__ float z [LAT];

    float s = 0.f;
#pragma unroll
    for (int i = 0; i < 32; i++) s += g_part[((long)b * 32 + i) * DD + t];
    xm[t] = s * (1.0f / (float)SS);
    __syncthreads();

    if (t < 256) {
        float a = be1[t];
        const float* w = we1 + (long)t * DD;
#pragma unroll 8
        for (int k = 0; k < DD; k++) a += xm[k] * w[k];
        h1[t] = fmaxf(a, 0.f);
    }
    __syncthreads();

    if (t < 128) {
        float a = be2[t];
        const float* w = we2 + (long)t * 256;
#pragma unroll 8
        for (int k = 0; k < 256; k++) a += h1[k] * w[k];
        h2[t] = fmaxf(a, 0.f);
    }
    __syncthreads();

    if (t < LAT) {
        float mu = bmu[t], lv = blv[t];
        const float* w1 = wmu + (long)t * 128;
        const float* w2 = wlv + (long)t * 128;
#pragma unroll 8
        for (int k = 0; k < 128; k++) { mu += h2[k] * w1[k]; lv += h2[k] * w2[k]; }
        out[(long)BB * SS * DD + b * LAT + t]            = mu;
        out[(long)BB * SS * DD + BB * LAT + b * LAT + t] = lv;
        z[t] = mu + eps[b * LAT + t] * expf(0.5f * lv);
    }
    __syncthreads();

    {
        float a = bf[t];
        const float* w = wf + (long)t * LAT;
#pragma unroll
        for (int k = 0; k < LAT; k++) a += z[k] * w[k];
        g_lat[b * DD + t] = a;
    }
}

// ---------------- 3) f16 GEMM: cp.async 3-stage + ldmatrix -------------------
// C = A @ W^T + bias (+latent). A,W f16; accum fp32. CTA 128x128, warps 4(M)x2(N).
// k-chunk 32. Row stride 40 halfs (80B) -> conflict-free ldsm.
// Modes: 0=Q (+lat, *1/8, f16, bhsd)  1=K (+lat, f16, bhsd)
//        2=V (f16, transposed (b,h,hd,s))  3=OUT (fp32)
#define G_CK      32
#define G_RSH     40
#define G_STG_B   (2 * 128 * G_RSH * 2)       // 20480 bytes per stage (A+W)
#define G_STAGES  3
#define GEMM_SMEM_BYTES (G_STAGES * G_STG_B)  // 61440

template <int MODE>
__global__ __launch_bounds__(256, 2) void gemm_f16(const __half* __restrict__ A,
                                                   const __half* __restrict__ W,
                                                   const float* __restrict__ bias,
                                                   void* __restrict__ out_) {
    extern __shared__ char smc[];
    uint32_t smb = (uint32_t)__cvta_generic_to_shared(smc);

    int tid  = threadIdx.x;
    int lane = tid & 31;
    int wid  = tid >> 5;
    int gID  = lane >> 2;
    int tig  = lane & 3;
    int wm   = wid & 3;
    int wn   = wid >> 2;
    int m0   = blockIdx.x * 128;
    int n0   = blockIdx.y * 128;

    int mtx = lane >> 3;
    int lr  = lane & 7;

    // producer: 512 segs each for A,W per stage; 2 per thread each
    auto prefetch = [&](int c, int st) {
#pragma unroll
        for (int i = 0; i < 2; i++) {
            int s = tid + i * 256;
            int r = s >> 2, ch = (s & 3) * 8;
            CP_A16(smb + st * G_STG_B + (r * G_RSH + ch) * 2,
                   A + (long)(m0 + r) * DD + c * G_CK + ch);
            CP_A16(smb + st * G_STG_B + 128 * G_RSH * 2 + (r * G_RSH + ch) * 2,
                   W + (long)(n0 + r) * DD + c * G_CK + ch);
        }
    };

    prefetch(0, 0); CP_COMMIT();
    prefetch(1, 1); CP_COMMIT();

    float acc[2][8][4] = {};

    // ldsm lane offsets
    int rowAoff = (mtx & 1) * 8 + lr;          // + wm*32 + mt*16
    int colAoff = (mtx >> 1) * 8;
    int rowBoff = (mtx >> 1) * 8 + lr;         // + wn*64 + nbp*16
    int colBoff = (mtx & 1) * 8;

    const int NCH = DD / G_CK;   // 16
    for (int c = 0; c < NCH; c++) {
        CP_WAIT(1);
        __syncthreads();
        if (c + 2 < NCH) prefetch(c + 2, (c + 2) % G_STAGES);
        CP_COMMIT();

        uint32_t stA = smb + (c % G_STAGES) * G_STG_B;
        uint32_t stW = stA + 128 * G_RSH * 2;

#pragma unroll
        for (int ks = 0; ks < 2; ks++) {
            uint32_t a[2][4];
#pragma unroll
            for (int mt = 0; mt < 2; mt++) {
                ldsm4(stA + ((wm * 32 + mt * 16 + rowAoff) * G_RSH + ks * 16 + colAoff) * 2,
                      a[mt][0], a[mt][1], a[mt][2], a[mt][3]);
            }
#pragma unroll
            for (int nbp = 0; nbp < 4; nbp++) {
                uint32_t b0, b1, b2, b3;
                ldsm4(stW + ((wn * 64 + nbp * 16 + rowBoff) * G_RSH + ks * 16 + colBoff) * 2,
                      b0, b1, b2, b3);
#pragma unroll
                for (int mt = 0; mt < 2; mt++) {
                    mma_f16(acc[mt][2 * nbp],     a[mt][0], a[mt][1], a[mt][2], a[mt][3], b0, b1);
                    mma_f16(acc[mt][2 * nbp + 1], a[mt][0], a[mt][1], a[mt][2], a[mt][3], b2, b3);
                }
            }
        }
    }

    // epilogue
    float*  outf = (float*)out_;
    __half* outh = (__half*)out_;
#pragma unroll
    for (int mt = 0; mt < 2; mt++) {
#pragma unroll
        for (int nb = 0; nb < 8; nb++) {
            int col = n0 + wn * 64 + (nb >> 1) * 16 + (nb & 1) * 8 + 2 * tig;
            float bz0 = bias[col], bz1 = bias[col + 1];
#pragma unroll
            for (int rr = 0; rr < 2; rr++) {
                int row = m0 + wm * 32 + mt * 16 + gID + 8 * rr;
                int b = row >> 12;
                int sidx = row & 4095;
                float v0 = acc[mt][nb][2 * rr + 0] + bz0;
                float v1 = acc[mt][nb][2 * rr + 1] + bz1;
                if (MODE == 0 || MODE == 1) {
                    v0 += g_lat[b * DD + col];
                    v1 += g_lat[b * DD + col + 1];
                    if (MODE == 0) { v0 *= 0.125f; v1 *= 0.125f; }
                    int h  = col >> 6;
                    int hd = col & 63;
                    *(__half2*)&outh[(((long)(b * HH + h) * SS + sidx) * HDD) + hd] =
                        __floats2half2_rn(v0, v1);
                } else if (MODE == 2) {
                    int h  = col >> 6;
                    int hd = col & 63;
                    long base = ((long)(b * HH + h) * HDD + hd) * SS + sidx;
                    outh[base]      = __float2half_rn(v0);
                    outh[base + SS] = __float2half_rn(v1);
                } else {
                    *(float2*)&outf[(long)row * DD + col] = make_float2(v0, v1);
                }
            }
        }
    }
}

// ---------------- 4) f16 flash attention ------------------------------------
// 128 q x 64 k tiles. 8 warps, warp = 16-row strip. m16n8k16, fp32 accum.
// Row-sum of P via MMA against constant ones B-fragment.
#define F_TB  (64 * 72 * 2)                 // 9216 bytes per tile
#define FLASH_SMEM_BYTES (4 * F_TB)         // 36864  [K0,K1,V0,V1]
#define ONESH2 0x3C003C00u

__global__ __launch_bounds__(256, 2) void flash_tc() {
    extern __shared__ char smc[];
    uint32_t smb = (uint32_t)__cvta_generic_to_shared(smc);

    int tid  = threadIdx.x;
    int lane = tid & 31;
    int wid  = tid >> 5;
    int gID  = lane >> 2;
    int tig  = lane & 3;
    int bh   = blockIdx.y;
    int m0   = blockIdx.x * 128;
    int m0w  = wid * 16;

    int grp = lane >> 3;
    int lr  = lane & 7;

    const __half* Qg = g_q + ((long)bh * SS + m0) * HDD;
    const __half* Kg = g_k + (long)bh * SS * HDD;
    const __half* Vg = g_v + (long)bh * HDD * SS;   // (hd, s)

    // ---- Q A-fragments from global (f16 pairs; prescaled 1/8) ----
    const uint32_t* Qg32 = (const uint32_t*)Qg;
    uint32_t qa[4][4];
#pragma unroll
    for (int ks = 0; ks < 4; ks++) {
        qa[ks][0] = Qg32[(m0w + gID)     * 32 + 8 * ks + tig];
        qa[ks][1] = Qg32[(m0w + gID + 8) * 32 + 8 * ks + tig];
        qa[ks][2] = Qg32[(m0w + gID)     * 32 + 8 * ks + tig + 4];
        qa[ks][3] = Qg32[(m0w + gID + 8) * 32 + 8 * ks + tig + 4];
    }

    auto prefetch = [&](int c, int st) {
#pragma unroll
        for (int i = 0; i < 2; i++) {
            int s = tid + i * 256;
            int r = s >> 3, ch = (s & 7) * 8;
            CP_A16(smb + st * F_TB + (r * 72 + ch) * 2,
                   Kg + (long)(c * 64 + r) * HDD + ch);
            CP_A16(smb + 2 * F_TB + st * F_TB + (r * 72 + ch) * 2,
                   Vg + (long)r * SS + c * 64 + ch);
        }
    };

    prefetch(0, 0); CP_COMMIT();

    float oacc[8][4] = {};
    float lsum[4] = {};
    float m0r = -1e30f, m1r = -1e30f;

    uint32_t lmBase = (((grp >> 1) * 8 + lr) * 72 + (grp & 1) * 8) * 2;

    const int NT = SS / 64;
    for (int c = 0; c < NT; c++) {
        CP_WAIT(0);
        __syncthreads();
        if (c + 1 < NT) prefetch(c + 1, (c + 1) & 1);
        CP_COMMIT();

        uint32_t stK = smb + (c & 1) * F_TB;
        uint32_t stV = smb + 2 * F_TB + (c & 1) * F_TB;

        // ---- S = Q @ K^T ----
        float sacc[8][4] = {};
#pragma unroll
        for (int ks = 0; ks < 4; ks++) {
#pragma unroll
            for (int nbp = 0; nbp < 4; nbp++) {
                uint32_t b0, b1, b2, b3;
                ldsm4(stK + lmBase + nbp * (16 * 144) + ks * 32, b0, b1, b2, b3);
                mma_f16(sacc[2 * nbp],     qa[ks][0], qa[ks][1], qa[ks][2], qa[ks][3], b0, b1);
                mma_f16(sacc[2 * nbp + 1], qa[ks][0], qa[ks][1], qa[ks][2], qa[ks][3], b2, b3);
            }
        }

        // ---- online softmax (warp-local quad reduction for max only) ----
        float mx0 = -1e30f, mx1 = -1e30f;
#pragma unroll
        for (int nb = 0; nb < 8; nb++) {
            mx0 = fmaxf(mx0, fmaxf(sacc[nb][0], sacc[nb][1]));
            mx1 = fmaxf(mx1, fmaxf(sacc[nb][2], sacc[nb][3]));
        }
        mx0 = fmaxf(mx0, __shfl_xor_sync(0xffffffffu, mx0, 1));
        mx0 = fmaxf(mx0, __shfl_xor_sync(0xffffffffu, mx0, 2));
        mx1 = fmaxf(mx1, __shfl_xor_sync(0xffffffffu, mx1, 1));
        mx1 = fmaxf(mx1, __shfl_xor_sync(0xffffffffu, mx1, 2));

        float nm0 = fmaxf(m0r, mx0);
        float nm1 = fmaxf(m1r, mx1);
        float c0 = __expf(m0r - nm0);
        float c1 = __expf(m1r - nm1);
        m0r = nm0; m1r = nm1;

        // P = exp(S - m), packed straight into f16 A-fragments
        uint32_t pa[4][4];
#pragma unroll
        for (int ks = 0; ks < 4; ks++) {
            float p00 = __expf(sacc[2 * ks][0] - nm0);
            float p01 = __expf(sacc[2 * ks][1] - nm0);
            float p02 = __expf(sacc[2 * ks][2] - nm1);
            float p03 = __expf(sacc[2 * ks][3] - nm1);
            float p10 = __expf(sacc[2 * ks + 1][0] - nm0);
            float p11 = __expf(sacc[2 * ks + 1][1] - nm0);
            float p12 = __expf(sacc[2 * ks + 1][2] - nm1);
            float p13 = __expf(sacc[2 * ks + 1][3] - nm1);
            pa[ks][0] = packh2(p00, p01);
            pa[ks][1] = packh2(p02, p03);
            pa[ks][2] = packh2(p10, p11);
            pa[ks][3] = packh2(p12, p13);
        }

        // rescale running accumulators
#pragma unroll
        for (int nb = 0; nb < 8; nb++) {
            oacc[nb][0] *= c0; oacc[nb][1] *= c0;
            oacc[nb][2] *= c1; oacc[nb][3] *= c1;
        }
        lsum[0] *= c0; lsum[1] *= c0;
        lsum[2] *= c1; lsum[3] *= c1;

        // ---- l += P @ ones  (row sums via tensor core) ----
#pragma unroll
        for (int ks = 0; ks < 4; ks++)
            mma_f16(lsum, pa[ks][0], pa[ks][1], pa[ks][2], pa[ks][3], ONESH2, ONESH2);

        // ---- O += P @ V ----
#pragma unroll
        for (int ks = 0; ks < 4; ks++) {
#pragma unroll
            for (int nbp = 0; nbp < 4; nbp++) {
                uint32_t v0, v1, v2, v3;
                ldsm4(stV + lmBase + nbp * (16 * 144) + ks * 32, v0, v1, v2, v3);
                mma_f16(oacc[2 * nbp],     pa[ks][0], pa[ks][1], pa[ks][2], pa[ks][3], v0, v1);
                mma_f16(oacc[2 * nbp + 1], pa[ks][0], pa[ks][1], pa[ks][2], pa[ks][3], v2, v3);
            }
        }
    }

    // ---- normalize + write ctx (b,s,d) f16 ----
    int b = bh >> 3, h = bh & 7;
    float inv0 = 1.0f / lsum[0];
    float inv1 = 1.0f / lsum[2];
#pragma unroll
    for (int nb = 0; nb < 8; nb++) {
        int dv = 8 * nb + 2 * tig;
        long row0 = (long)b * SS + m0 + m0w + gID;
        long row1 = row0 + 8;
        *(__half2*)&g_ctx[row0 * DD + h * HDD + dv] =
            __floats2half2_rn(oacc[nb][0] * inv0, oacc[nb][1] * inv0);
        *(__half2*)&g_ctx[row1 * DD + h * HDD + dv] =
            __floats2half2_rn(oacc[nb][2] * inv1, oacc[nb][3] * inv1);
    }
}

// ---------------- launch ----------------
extern "C" void kernel_launch(void* const* d_in, const int* in_sizes, int n_in,
                              void* d_out, int out_size) {
    const float* x   = (const float*)d_in[0];
    const float* eps = (const float*)d_in[1];
    const float* wq  = (const float*)d_in[2];  const float* bq  = (const float*)d_in[3];
    const float* wk  = (const float*)d_in[4];  const float* bk  = (const float*)d_in[5];
    const float* wv  = (const float*)d_in[6];  const float* bv  = (const float*)d_in[7];
    const float* wo  = (const float*)d_in[8];  const float* bo  = (const float*)d_in[9];
    const float* we1 = (const float*)d_in[10]; const float* be1 = (const float*)d_in[11];
    const float* we2 = (const float*)d_in[12]; const float* be2 = (const float*)d_in[13];
    const float* wmu = (const float*)d_in[14]; const float* bmu = (const float*)d_in[15];
    const float* wlv = (const float*)d_in[16]; const float* blv = (const float*)d_in[17];
    const float* wf  = (const float*)d_in[18]; const float* bf  = (const float*)d_in[19];
    float* out = (float*)d_out;

    void *pxh, *pwh, *pq, *pk, *pv, *pctx;
    cudaGetSymbolAddress(&pxh, g_xh);
    cudaGetSymbolAddress(&pwh, g_wh);
    cudaGetSymbolAddress(&pq,  g_q);
    cudaGetSymbolAddress(&pk,  g_k);
    cudaGetSymbolAddress(&pv,  g_v);
    cudaGetSymbolAddress(&pctx, g_ctx);
    const __half* xh = (const __half*)pxh;
    const __half* wh = (const __half*)pwh;

    cudaFuncSetAttribute(gemm_f16<0>, cudaFuncAttributeMaxDynamicSharedMemorySize, GEMM_SMEM_BYTES);
    cudaFuncSetAttribute(gemm_f16<1>, cudaFuncAttributeMaxDynamicSharedMemorySize, GEMM_SMEM_BYTES);
    cudaFuncSetAttribute(gemm_f16<2>, cudaFuncAttributeMaxDynamicSharedMemorySize, GEMM_SMEM_BYTES);
    cudaFuncSetAttribute(gemm_f16<3>, cudaFuncAttributeMaxDynamicSharedMemorySize, GEMM_SMEM_BYTES);
    cudaFuncSetAttribute(flash_tc, cudaFuncAttributeMaxDynamicSharedMemorySize, FLASH_SMEM_BYTES);

    conv_weights<<<DD * DD / 256, 256>>>(wq, wk, wv, wo);
    mean_partial<<<BB * 32, DD>>>(x);
    vae_kernel<<<BB, DD>>>(eps, we1, be1, we2, be2, wmu, bmu, wlv, blv, wf, bf, out);

    dim3 gg((BB * SS) / 128, DD / 128);
    gemm_f16<0><<<gg, 256, GEMM_SMEM_BYTES>>>(xh, wh,               bq, pq);
    gemm_f16<1><<<gg, 256, GEMM_SMEM_BYTES>>>(xh, wh + DD * DD,     bk, pk);
    gemm_f16<2><<<gg, 256, GEMM_SMEM_BYTES>>>(xh, wh + 2 * DD * DD, bv, pv);

    flash_tc<<<dim3(SS / 128, BB * HH), 256, FLASH_SMEM_BYTES>>>();

    gemm_f16<3><<<gg, 256, GEMM_SMEM_BYTES>>>((const __half*)pctx, wh + 3 * DD * DD, bo, out);
}

// round 11
// speedup vs baseline: 5.5456x; 1.0043x over previous
#include <cuda_runtime.h>
#include <cuda_fp16.h>
#include <math.h>
#include <stdint.h>

#define BB   2
#define SS   4096
#define DD   512
#define HH   8
#define HDD  64
#define LAT  64

// ---------------- scratch (static device globals; no allocs) ----------------
__device__ float  g_part[BB * 32 * DD];
__device__ float  g_lat [BB * DD];
__device__ __half g_xh  [BB * SS * DD];         // x in f16
__device__ __half g_wh  [4 * DD * DD];          // wq,wk,wv,wo in f16
__device__ __half g_q   [BB * HH * SS * HDD];   // (b,h,s,hd) f16, prescaled log2e/8
__device__ __half g_k   [BB * HH * SS * HDD];   // (b,h,s,hd) f16
__device__ __half g_v   [BB * HH * HDD * SS];   // (b,h,hd,s) f16 (TRANSPOSED)
__device__ __half g_ctx [BB * SS * DD];         // (b,s,d) f16

#define QSCALE 0.18033688011112042f            // log2(e)/8

// ---------------- helpers ----------------
__device__ __forceinline__ float u2f(uint32_t u) { return __uint_as_float(u); }

__device__ __forceinline__ float ex2f(float x) {
    float r; asm("ex2.approx.f32 %0, %1;" : "=f"(r) : "f"(x)); return r;
}

// pack {lo, hi} floats -> f16x2 reg
__device__ __forceinline__ uint32_t packh2(float lo, float hi) {
    uint32_t d;
    asm("cvt.rn.f16x2.f32 %0, %1, %2;" : "=r"(d) : "f"(hi), "f"(lo));
    return d;
}

// 2^x on both f16 halves
__device__ __forceinline__ uint32_t hex2(uint32_t x) {
    uint32_t r;
    asm("ex2.approx.f16x2 %0, %1;" : "=r"(r) : "r"(x));
    return r;
}

__device__ __forceinline__ void mma_f16(float* c, uint32_t a0, uint32_t a1,
                                        uint32_t a2, uint32_t a3,
                                        uint32_t b0, uint32_t b1) {
    asm volatile(
        "mma.sync.aligned.m16n8k16.row.col.f32.f16.f16.f32 "
        "{%0,%1,%2,%3}, {%4,%5,%6,%7}, {%8,%9}, {%0,%1,%2,%3};\n"
        : "+f"(c[0]), "+f"(c[1]), "+f"(c[2]), "+f"(c[3])
        : "r"(a0), "r"(a1), "r"(a2), "r"(a3), "r"(b0), "r"(b1));
}

__device__ __forceinline__ void ldsm4(uint32_t addr, uint32_t& r0, uint32_t& r1,
                                      uint32_t& r2, uint32_t& r3) {
    asm volatile("ldmatrix.sync.aligned.m8n8.x4.shared.b16 {%0,%1,%2,%3}, [%4];\n"
                 : "=r"(r0), "=r"(r1), "=r"(r2), "=r"(r3) : "r"(addr));
}

#define CP_A16(dst, src) \
    asm volatile("cp.async.ca.shared.global [%0], [%1], 16;\n" :: "r"(dst), "l"(src))
#define CP_COMMIT() asm volatile("cp.async.commit_group;\n" ::: "memory")
#define CP_WAIT(n)  asm volatile("cp.async.wait_group %0;\n" :: "n"(n) : "memory")

// ---------------- 1) fused prep: mean partials + x->f16 + weights->f16 ------
__global__ void prep_kernel(const float* __restrict__ x,
                            const float* __restrict__ wq, const float* __restrict__ wk,
                            const float* __restrict__ wv, const float* __restrict__ wo) {
    int bx = blockIdx.x;
    int t  = threadIdx.x;           // 512
    if (bx < BB * 32) {
        int b  = bx >> 5;
        int sp = bx & 31;
        const int chunk = SS / 32;  // 128
        long base = ((long)b * SS + (long)sp * chunk) * DD + t;
        const float* p = x + base;
        float s = 0.f;
#pragma unroll 4
        for (int i = 0; i < chunk; i++) {
            float v = p[(long)i * DD];
            s += v;
            g_xh[base + (long)i * DD] = __float2half_rn(v);
        }
        g_part[(long)bx * DD + t] = s;
    } else {
        int i = (bx - BB * 32) * 512 + t;       // 0 .. 262143
        g_wh[i]                  = __float2half_rn(wq[i]);
        g_wh[DD * DD + i]        = __float2half_rn(wk[i]);
        g_wh[2 * DD * DD + i]    = __float2half_rn(wv[i]);
        g_wh[3 * DD * DD + i]    = __float2half_rn(wo[i]);
    }
}

// ---------------- 2) VAE MLP ----------------
__global__ void vae_kernel(const float* __restrict__ eps,
                           const float* __restrict__ we1, const float* __restrict__ be1,
                           const float* __restrict__ we2, const float* __restrict__ be2,
                           const float* __restrict__ wmu, const float* __restrict__ bmu,
                           const float* __restrict__ wlv, const float* __restrict__ blv,
                           const float* __restrict__ wf,  const float* __restrict__ bf,
                           float* __restrict__ out) {
    int b = blockIdx.x;
    int t = threadIdx.x;            // 512
    __shared__ float xm[DD];
    __shared__ float h1[256];
    __shared__ float h2[128];
    __shared__ float z [LAT];

    float s = 0.f;
#pragma unroll
    for (int i = 0; i < 32; i++) s += g_part[((long)b * 32 + i) * DD + t];
    xm[t] = s * (1.0f / (float)SS);
    __syncthreads();

    if (t < 256) {
        float a = be1[t];
        const float* w = we1 + (long)t * DD;
#pragma unroll 8
        for (int k = 0; k < DD; k++) a += xm[k] * w[k];
        h1[t] = fmaxf(a, 0.f);
    }
    __syncthreads();

    if (t < 128) {
        float a = be2[t];
        const float* w = we2 + (long)t * 256;
#pragma unroll 8
        for (int k = 0; k < 256; k++) a += h1[k] * w[k];
        h2[t] = fmaxf(a, 0.f);
    }
    __syncthreads();

    if (t < LAT) {
        float mu = bmu[t], lv = blv[t];
        const float* w1 = wmu + (long)t * 128;
        const float* w2 = wlv + (long)t * 128;
#pragma unroll 8
        for (int k = 0; k < 128; k++) { mu += h2[k] * w1[k]; lv += h2[k] * w2[k]; }
        out[(long)BB * SS * DD + b * LAT + t]            = mu;
        out[(long)BB * SS * DD + BB * LAT + b * LAT + t] = lv;
        z[t] = mu + eps[b * LAT + t] * expf(0.5f * lv);
    }
    __syncthreads();

    {
        float a = bf[t];
        const float* w = wf + (long)t * LAT;
#pragma unroll
        for (int k = 0; k < LAT; k++) a += z[k] * w[k];
        g_lat[b * DD + t] = a;
    }
}

// ---------------- 3) f16 GEMM: cp.async 3-stage + ldmatrix, merged QKV ------
// C = A @ W^T + bias (+latent). CTA 128x128, warps 4(M)x2(N), k-chunk 32.
// mode = mode0 + blockIdx.z:
//   0=Q (+lat, *log2e/8, f16, bhsd)  1=K (+lat, f16, bhsd)
//   2=V (f16, transposed (b,h,hd,s)) 3=OUT (fp32)
#define G_CK      32
#define G_RSH     40
#define G_STG_B   (2 * 128 * G_RSH * 2)       // 20480 bytes per stage (A+W)
#define G_STAGES  3
#define GEMM_SMEM_BYTES (G_STAGES * G_STG_B)  // 61440

__global__ __launch_bounds__(256, 2) void gemm_f16m(const __half* __restrict__ A,
                                                    const __half* __restrict__ Wb,
                                                    const float* __restrict__ b0,
                                                    const float* __restrict__ b1,
                                                    const float* __restrict__ b2,
                                                    float* __restrict__ outp, int mode0) {
    extern __shared__ char smc[];
    uint32_t smb = (uint32_t)__cvta_generic_to_shared(smc);

    int tid  = threadIdx.x;
    int lane = tid & 31;
    int wid  = tid >> 5;
    int gID  = lane >> 2;
    int tig  = lane & 3;
    int wm   = wid & 3;
    int wn   = wid >> 2;
    int m0   = blockIdx.x * 128;
    int n0   = blockIdx.y * 128;
    int z    = blockIdx.z;
    const __half* W    = Wb + (long)z * DD * DD;
    const float*  bias = (z == 0) ? b0 : (z == 1 ? b1 : b2);
    int mode = mode0 + z;

    int mtx = lane >> 3;
    int lr  = lane & 7;

    auto prefetch = [&](int c, int st) {
#pragma unroll
        for (int i = 0; i < 2; i++) {
            int s = tid + i * 256;
            int r = s >> 2, ch = (s & 3) * 8;
            CP_A16(smb + st * G_STG_B + (r * G_RSH + ch) * 2,
                   A + (long)(m0 + r) * DD + c * G_CK + ch);
            CP_A16(smb + st * G_STG_B + 128 * G_RSH * 2 + (r * G_RSH + ch) * 2,
                   W + (long)(n0 + r) * DD + c * G_CK + ch);
        }
    };

    prefetch(0, 0); CP_COMMIT();
    prefetch(1, 1); CP_COMMIT();

    float acc[2][8][4] = {};

    int rowAoff = (mtx & 1) * 8 + lr;
    int colAoff = (mtx >> 1) * 8;
    int rowBoff = (mtx >> 1) * 8 + lr;
    int colBoff = (mtx & 1) * 8;

    const int NCH = DD / G_CK;   // 16
    for (int c = 0; c < NCH; c++) {
        CP_WAIT(1);
        __syncthreads();
        if (c + 2 < NCH) prefetch(c + 2, (c + 2) % G_STAGES);
        CP_COMMIT();

        uint32_t stA = smb + (c % G_STAGES) * G_STG_B;
        uint32_t stW = stA + 128 * G_RSH * 2;

#pragma unroll
        for (int ks = 0; ks < 2; ks++) {
            uint32_t a[2][4];
#pragma unroll
            for (int mt = 0; mt < 2; mt++) {
                ldsm4(stA + ((wm * 32 + mt * 16 + rowAoff) * G_RSH + ks * 16 + colAoff) * 2,
                      a[mt][0], a[mt][1], a[mt][2], a[mt][3]);
            }
#pragma unroll
            for (int nbp = 0; nbp < 4; nbp++) {
                uint32_t b0r, b1r, b2r, b3r;
                ldsm4(stW + ((wn * 64 + nbp * 16 + rowBoff) * G_RSH + ks * 16 + colBoff) * 2,
                      b0r, b1r, b2r, b3r);
#pragma unroll
                for (int mt = 0; mt < 2; mt++) {
                    mma_f16(acc[mt][2 * nbp],     a[mt][0], a[mt][1], a[mt][2], a[mt][3], b0r, b1r);
                    mma_f16(acc[mt][2 * nbp + 1], a[mt][0], a[mt][1], a[mt][2], a[mt][3], b2r, b3r);
                }
            }
        }
    }

    // epilogue
#pragma unroll
    for (int mt = 0; mt < 2; mt++) {
#pragma unroll
        for (int nb = 0; nb < 8; nb++) {
            int col = n0 + wn * 64 + (nb >> 1) * 16 + (nb & 1) * 8 + 2 * tig;
            float bz0 = bias[col], bz1 = bias[col + 1];
#pragma unroll
            for (int rr = 0; rr < 2; rr++) {
                int row = m0 + wm * 32 + mt * 16 + gID + 8 * rr;
                int b = row >> 12;
                int sidx = row & 4095;
                float v0 = acc[mt][nb][2 * rr + 0] + bz0;
                float v1 = acc[mt][nb][2 * rr + 1] + bz1;
                if (mode <= 1) {
                    v0 += g_lat[b * DD + col];
                    v1 += g_lat[b * DD + col + 1];
                    if (mode == 0) { v0 *= QSCALE; v1 *= QSCALE; }
                    int h  = col >> 6;
                    int hd = col & 63;
                    __half* dst = (mode == 0) ? g_q : g_k;
                    *(__half2*)&dst[(((long)(b * HH + h) * SS + sidx) * HDD) + hd] =
                        __floats2half2_rn(v0, v1);
                } else if (mode == 2) {
                    int h  = col >> 6;
                    int hd = col & 63;
                    long base = ((long)(b * HH + h) * HDD + hd) * SS + sidx;
                    g_v[base]      = __float2half_rn(v0);
                    g_v[base + SS] = __float2half_rn(v1);
                } else {
                    *(float2*)&outp[(long)row * DD + col] = make_float2(v0, v1);
                }
            }
        }
    }
}

// ---------------- 4) f16 flash attention (log2-domain softmax, hex2) --------
#define F_TB  (64 * 72 * 2)                 // 9216 bytes per tile
#define FLASH_SMEM_BYTES (4 * F_TB)         // 36864  [K0,K1,V0,V1]
#define ONESH2 0x3C003C00u

__global__ __launch_bounds__(256, 2) void flash_tc() {
    extern __shared__ char smc[];
    uint32_t smb = (uint32_t)__cvta_generic_to_shared(smc);

    int tid  = threadIdx.x;
    int lane = tid & 31;
    int wid  = tid >> 5;
    int gID  = lane >> 2;
    int tig  = lane & 3;
    int bh   = blockIdx.y;
    int m0   = blockIdx.x * 128;
    int m0w  = wid * 16;

    int grp = lane >> 3;
    int lr  = lane & 7;

    const __half* Qg = g_q + ((long)bh * SS + m0) * HDD;
    const __half* Kg = g_k + (long)bh * SS * HDD;
    const __half* Vg = g_v + (long)bh * HDD * SS;   // (hd, s)

    const uint32_t* Qg32 = (const uint32_t*)Qg;
    uint32_t qa[4][4];
#pragma unroll
    for (int ks = 0; ks < 4; ks++) {
        qa[ks][0] = Qg32[(m0w + gID)     * 32 + 8 * ks + tig];
        qa[ks][1] = Qg32[(m0w + gID + 8) * 32 + 8 * ks + tig];
        qa[ks][2] = Qg32[(m0w + gID)     * 32 + 8 * ks + tig + 4];
        qa[ks][3] = Qg32[(m0w + gID + 8) * 32 + 8 * ks + tig + 4];
    }

    auto prefetch = [&](int c, int st) {
#pragma unroll
        for (int i = 0; i < 2; i++) {
            int s = tid + i * 256;
            int r = s >> 3, ch = (s & 7) * 8;
            CP_A16(smb + st * F_TB + (r * 72 + ch) * 2,
                   Kg + (long)(c * 64 + r) * HDD + ch);
            CP_A16(smb + 2 * F_TB + st * F_TB + (r * 72 + ch) * 2,
                   Vg + (long)r * SS + c * 64 + ch);
        }
    };

    prefetch(0, 0); CP_COMMIT();

    float oacc[8][4] = {};
    float lsum[4] = {};
    float m0r = -1e30f, m1r = -1e30f;

    uint32_t lmBase = (((grp >> 1) * 8 + lr) * 72 + (grp & 1) * 8) * 2;

    const int NT = SS / 64;
    for (int c = 0; c < NT; c++) {
        CP_WAIT(0);
        __syncthreads();
        if (c + 1 < NT) prefetch(c + 1, (c + 1) & 1);
        CP_COMMIT();

        uint32_t stK = smb + (c & 1) * F_TB;
        uint32_t stV = smb + 2 * F_TB + (c & 1) * F_TB;

        // ---- S = Q @ K^T (scores already in log2 domain via Q prescale) ----
        float sacc[8][4] = {};
#pragma unroll
        for (int ks = 0; ks < 4; ks++) {
#pragma unroll
            for (int nbp = 0; nbp < 4; nbp++) {
                uint32_t b0, b1, b2, b3;
                ldsm4(stK + lmBase + nbp * (16 * 144) + ks * 32, b0, b1, b2, b3);
                mma_f16(sacc[2 * nbp],     qa[ks][0], qa[ks][1], qa[ks][2], qa[ks][3], b0, b1);
                mma_f16(sacc[2 * nbp + 1], qa[ks][0], qa[ks][1], qa[ks][2], qa[ks][3], b2, b3);
            }
        }

        // ---- online softmax ----
        float mx0 = -1e30f, mx1 = -1e30f;
#pragma unroll
        for (int nb = 0; nb < 8; nb++) {
            mx0 = fmaxf(mx0, fmaxf(sacc[nb][0], sacc[nb][1]));
            mx1 = fmaxf(mx1, fmaxf(sacc[nb][2], sacc[nb][3]));
        }
        mx0 = fmaxf(mx0, __shfl_xor_sync(0xffffffffu, mx0, 1));
        mx0 = fmaxf(mx0, __shfl_xor_sync(0xffffffffu, mx0, 2));
        mx1 = fmaxf(mx1, __shfl_xor_sync(0xffffffffu, mx1, 1));
        mx1 = fmaxf(mx1, __shfl_xor_sync(0xffffffffu, mx1, 2));

        float nm0 = fmaxf(m0r, mx0);
        float nm1 = fmaxf(m1r, mx1);
        float c0 = ex2f(m0r - nm0);
        float c1 = ex2f(m1r - nm1);
        m0r = nm0; m1r = nm1;

        // P = 2^(S - m): f32 subtract (accuracy near max), packed f16x2 exp
        uint32_t pa[4][4];
#pragma unroll
        for (int ks = 0; ks < 4; ks++) {
            pa[ks][0] = hex2(packh2(sacc[2 * ks][0] - nm0, sacc[2 * ks][1] - nm0));
            pa[ks][1] = hex2(packh2(sacc[2 * ks][2] - nm1, sacc[2 * ks][3] - nm1));
            pa[ks][2] = hex2(packh2(sacc[2 * ks + 1][0] - nm0, sacc[2 * ks + 1][1] - nm0));
            pa[ks][3] = hex2(packh2(sacc[2 * ks + 1][2] - nm1, sacc[2 * ks + 1][3] - nm1));
        }

#pragma unroll
        for (int nb = 0; nb < 8; nb++) {
            oacc[nb][0] *= c0; oacc[nb][1] *= c0;
            oacc[nb][2] *= c1; oacc[nb][3] *= c1;
        }
        lsum[0] *= c0; lsum[1] *= c0;
        lsum[2] *= c1; lsum[3] *= c1;

        // ---- l += P @ ones ----
#pragma unroll
        for (int ks = 0; ks < 4; ks++)
            mma_f16(lsum, pa[ks][0], pa[ks][1], pa[ks][2], pa[ks][3], ONESH2, ONESH2);

        // ---- O += P @ V ----
#pragma unroll
        for (int ks = 0; ks < 4; ks++) {
#pragma unroll
            for (int nbp = 0; nbp < 4; nbp++) {
                uint32_t v0, v1, v2, v3;
                ldsm4(stV + lmBase + nbp * (16 * 144) + ks * 32, v0, v1, v2, v3);
                mma_f16(oacc[2 * nbp],     pa[ks][0], pa[ks][1], pa[ks][2], pa[ks][3], v0, v1);
                mma_f16(oacc[2 * nbp + 1], pa[ks][0], pa[ks][1], pa[ks][2], pa[ks][3], v2, v3);
            }
        }
    }

    // ---- normalize + write ctx (b,s,d) f16 ----
    int b = bh >> 3, h = bh & 7;
    float inv0 = 1.0f / lsum[0];
    float inv1 = 1.0f / lsum[2];
#pragma unroll
    for (int nb = 0; nb < 8; nb++) {
        int dv = 8 * nb + 2 * tig;
        long row0 = (long)b * SS + m0 + m0w + gID;
        long row1 = row0 + 8;
        *(__half2*)&g_ctx[row0 * DD + h * HDD + dv] =
            __floats2half2_rn(oacc[nb][0] * inv0, oacc[nb][1] * inv0);
        *(__half2*)&g_ctx[row1 * DD + h * HDD + dv] =
            __floats2half2_rn(oacc[nb][2] * inv1, oacc[nb][3] * inv1);
    }
}

// ---------------- launch ----------------
extern "C" void kernel_launch(void* const* d_in, const int* in_sizes, int n_in,
                              void* d_out, int out_size) {
    const float* x   = (const float*)d_in[0];
    const float* eps = (const float*)d_in[1];
    const float* wq  = (const float*)d_in[2];  const float* bq  = (const float*)d_in[3];
    const float* wk  = (const float*)d_in[4];  const float* bk  = (const float*)d_in[5];
    const float* wv  = (const float*)d_in[6];  const float* bv  = (const float*)d_in[7];
    const float* wo  = (const float*)d_in[8];  const float* bo  = (const float*)d_in[9];
    const float* we1 = (const float*)d_in[10]; const float* be1 = (const float*)d_in[11];
    const float* we2 = (const float*)d_in[12]; const float* be2 = (const float*)d_in[13];
    const float* wmu = (const float*)d_in[14]; const float* bmu = (const float*)d_in[15];
    const float* wlv = (const float*)d_in[16]; const float* blv = (const float*)d_in[17];
    const float* wf  = (const float*)d_in[18]; const float* bf  = (const float*)d_in[19];
    float* out = (float*)d_out;

    void *pxh, *pwh, *pctx;
    cudaGetSymbolAddress(&pxh, g_xh);
    cudaGetSymbolAddress(&pwh, g_wh);
    cudaGetSymbolAddress(&pctx, g_ctx);
    const __half* xh = (const __half*)pxh;
    const __half* wh = (const __half*)pwh;

    cudaFuncSetAttribute(gemm_f16m, cudaFuncAttributeMaxDynamicSharedMemorySize, GEMM_SMEM_BYTES);
    cudaFuncSetAttribute(flash_tc, cudaFuncAttributeMaxDynamicSharedMemorySize, FLASH_SMEM_BYTES);

    // fused prep: mean partials + x->f16 (blocks 0..63) and weights->f16 (64..575)
    prep_kernel<<<BB * 32 + 512, 512>>>(x, wq, wk, wv, wo);
    vae_kernel<<<BB, DD>>>(eps, we1, be1, we2, be2, wmu, bmu, wlv, blv, wf, bf, out);

    // merged Q/K/V projections (z = 0,1,2 -> mode)
    gemm_f16m<<<dim3((BB * SS) / 128, DD / 128, 3), 256, GEMM_SMEM_BYTES>>>(
        xh, wh, bq, bk, bv, nullptr, 0);

    flash_tc<<<dim3(SS / 128, BB * HH), 256, FLASH_SMEM_BYTES>>>();

    // output projection (mode 3)
    gemm_f16m<<<dim3((BB * SS) / 128, DD / 128, 1), 256, GEMM_SMEM_BYTES>>>(
        (const __half*)pctx, wh + 3 * DD * DD, bo, nullptr, nullptr, out, 3);
}